// round 1
// baseline (speedup 1.0000x reference)
#include <cuda_runtime.h>
#include <math.h>

#define RTOT  8192              // B*N rows
#define SEQ   4096              // per-batch sequence length
#define DIM   1024
#define BANDW 640               // padded band width per row-block
#define LN_EPS 1e-6f
#define RD (RTOT * DIM)

// Scratch layout (floats): K, Q, V, A, ySum, band
__device__ float g_scratch[5 * RD + (size_t)RTOT * BANDW];

// ---------------------------------------------------------------------------
// Generic SGEMM: C[M,N] = alpha * (A[M,K] @ B[N,K]^T) (+bias[N]) (+ReLU)
// 128x128 tile, BK=8, 256 threads, 8x8 per thread.
// Requires M,N multiples of 128 and K multiple of 8 (true for all calls).
// ---------------------------------------------------------------------------
__global__ void __launch_bounds__(256, 2)
sgemm128(const float* __restrict__ A, const float* __restrict__ B,
         const float* __restrict__ bias, float* __restrict__ C,
         int Nn, int Kd, float alpha, int relu)
{
    __shared__ float As[8][128];
    __shared__ float Bs[8][128];
    const int bm = blockIdx.y << 7;
    const int bn = blockIdx.x << 7;
    const int tid = threadIdx.x;
    const int lr = tid >> 1;            // 0..127 tile row for loads
    const int ls = (tid & 1) << 2;      // 0 or 4 k-offset for loads
    const int tx = tid & 15;
    const int ty = tid >> 4;

    const float* Ap = A + (size_t)(bm + lr) * Kd + ls;
    const float* Bp = B + (size_t)(bn + lr) * Kd + ls;

    float acc[8][8];
#pragma unroll
    for (int i = 0; i < 8; i++)
#pragma unroll
        for (int j = 0; j < 8; j++) acc[i][j] = 0.f;

    for (int k0 = 0; k0 < Kd; k0 += 8) {
        float4 av = *(const float4*)(Ap + k0);
        float4 bv = *(const float4*)(Bp + k0);
        __syncthreads();
        As[ls + 0][lr] = av.x; As[ls + 1][lr] = av.y;
        As[ls + 2][lr] = av.z; As[ls + 3][lr] = av.w;
        Bs[ls + 0][lr] = bv.x; Bs[ls + 1][lr] = bv.y;
        Bs[ls + 2][lr] = bv.z; Bs[ls + 3][lr] = bv.w;
        __syncthreads();
#pragma unroll
        for (int k = 0; k < 8; k++) {
            float4 a0 = *(const float4*)&As[k][ty << 3];
            float4 a1 = *(const float4*)&As[k][(ty << 3) + 4];
            float4 b0 = *(const float4*)&Bs[k][tx << 3];
            float4 b1 = *(const float4*)&Bs[k][(tx << 3) + 4];
            float a[8] = {a0.x, a0.y, a0.z, a0.w, a1.x, a1.y, a1.z, a1.w};
            float b[8] = {b0.x, b0.y, b0.z, b0.w, b1.x, b1.y, b1.z, b1.w};
#pragma unroll
            for (int i = 0; i < 8; i++)
#pragma unroll
                for (int j = 0; j < 8; j++)
                    acc[i][j] = fmaf(a[i], b[j], acc[i][j]);
        }
    }

#pragma unroll
    for (int i = 0; i < 8; i++) {
        const size_t m = (size_t)bm + (ty << 3) + i;
#pragma unroll
        for (int j = 0; j < 8; j++) {
            const int n = bn + (tx << 3) + j;
            float v = alpha * acc[i][j];
            if (bias) v += bias[n];
            if (relu) v = fmaxf(v, 0.f);
            C[m * Nn + n] = v;
        }
    }
}

// ---------------------------------------------------------------------------
// Band logits: for row-block rb (64 rows, i0=rb*64) store
//   band[i][c] = Q[i] . K[jstart + c],  jstart = i0 - 256, c in [0,640)
// Grid: (cb=0..9, rb=0..127). 64x64 tile per block, BK=16, 4x4 per thread.
// Out-of-range K rows contribute garbage zeros; softmax masks them.
// ---------------------------------------------------------------------------
__global__ void __launch_bounds__(256)
band_logits(const float* __restrict__ Q, const float* __restrict__ Kk,
            float* __restrict__ band)
{
    __shared__ float Qs[16][64];
    __shared__ float Ks[16][64];
    const int rb = blockIdx.y, cb = blockIdx.x;
    const int i0 = rb << 6;
    const int j0 = i0 - 256 + (cb << 6);
    const int tid = threadIdx.x;
    const int lr = tid >> 2;            // 0..63
    const int ls = (tid & 3) << 2;      // 0,4,8,12
    const int tx = tid & 15, ty = tid >> 4;

    const float* Qp = Q + (size_t)(i0 + lr) * DIM + ls;
    const int jrow = j0 + lr;
    const bool kok = (jrow >= 0) && (jrow < RTOT);
    const float* Kp = Kk + (size_t)(kok ? jrow : 0) * DIM + ls;

    float acc[4][4] = {};
    for (int k0 = 0; k0 < DIM; k0 += 16) {
        float4 qv = *(const float4*)(Qp + k0);
        float4 kv = kok ? *(const float4*)(Kp + k0) : make_float4(0.f, 0.f, 0.f, 0.f);
        __syncthreads();
        Qs[ls + 0][lr] = qv.x; Qs[ls + 1][lr] = qv.y;
        Qs[ls + 2][lr] = qv.z; Qs[ls + 3][lr] = qv.w;
        Ks[ls + 0][lr] = kv.x; Ks[ls + 1][lr] = kv.y;
        Ks[ls + 2][lr] = kv.z; Ks[ls + 3][lr] = kv.w;
        __syncthreads();
#pragma unroll
        for (int k = 0; k < 16; k++) {
            float4 a4 = *(const float4*)&Qs[k][ty << 2];
            float4 b4 = *(const float4*)&Ks[k][tx << 2];
            float a[4] = {a4.x, a4.y, a4.z, a4.w};
            float b[4] = {b4.x, b4.y, b4.z, b4.w};
#pragma unroll
            for (int i = 0; i < 4; i++)
#pragma unroll
                for (int j = 0; j < 4; j++)
                    acc[i][j] = fmaf(a[i], b[j], acc[i][j]);
        }
    }
#pragma unroll
    for (int i = 0; i < 4; i++) {
        const size_t off = (size_t)(i0 + (ty << 2) + i) * BANDW + (cb << 6) + (tx << 2);
        float4 v = make_float4(acc[i][0], acc[i][1], acc[i][2], acc[i][3]);
        *(float4*)(band + off) = v;
    }
}

// ---------------------------------------------------------------------------
// Masked row softmax over the band; invalid positions set to weight 0.
// Valid j: |i-j| < 256 AND j within i's batch.
// ---------------------------------------------------------------------------
__global__ void band_softmax(float* __restrict__ band)
{
    __shared__ float red[256];
    const int i = blockIdx.x;
    const int tid = threadIdx.x;
    const int i0 = i & ~63;
    const int jstart = i0 - 256;
    const int bs = (i < SEQ) ? 0 : SEQ;
    const int jmin = max(i - 255, bs);
    const int jmax = min(i + 255, bs + SEQ - 1);
    const int cmin = jmin - jstart, cmax = jmax - jstart;
    float* row = band + (size_t)i * BANDW;

    float m = -1e30f;
    for (int c = tid; c < BANDW; c += 256)
        if (c >= cmin && c <= cmax) m = fmaxf(m, row[c]);
    red[tid] = m; __syncthreads();
    for (int s = 128; s > 0; s >>= 1) {
        if (tid < s) red[tid] = fmaxf(red[tid], red[tid + s]);
        __syncthreads();
    }
    m = red[0]; __syncthreads();

    float ssum = 0.f;
    for (int c = tid; c < BANDW; c += 256)
        if (c >= cmin && c <= cmax) ssum += __expf(row[c] - m);
    red[tid] = ssum; __syncthreads();
    for (int s = 128; s > 0; s >>= 1) {
        if (tid < s) red[tid] += red[tid + s];
        __syncthreads();
    }
    const float inv = 1.f / red[0];

    for (int c = tid; c < BANDW; c += 256) {
        float v = (c >= cmin && c <= cmax) ? __expf(row[c] - m) * inv : 0.f;
        row[c] = v;
    }
}

// ---------------------------------------------------------------------------
// Transposed band apply: Y[n,d] = sum_m w[m,n] * V[m,d] for m in band(n).
// Grid: (dt=0..15, nb=0..127). For n-block n0, m-blocks m0 = n0-256+cb*64,
// cb=0..8; within m's band row, column of n is coff+ln with coff = 512-cb*64.
// ---------------------------------------------------------------------------
__global__ void __launch_bounds__(256)
band_apply(const float* __restrict__ band, const float* __restrict__ V,
           float* __restrict__ Y)
{
    __shared__ float Ws[16][64];
    __shared__ float Vs[16][64];
    const int nb = blockIdx.y, dt = blockIdx.x;
    const int n0 = nb << 6, d0 = dt << 6;
    const int tid = threadIdx.x;
    const int lr = tid >> 4;            // 0..15 m within chunk
    const int lc = (tid & 15) << 2;     // 0..60 column
    const int tx = tid & 15, ty = tid >> 4;

    float acc[4][4] = {};
    for (int cb = 0; cb < 9; cb++) {
        const int m0 = n0 - 256 + (cb << 6);
        const int coff = 512 - (cb << 6);
        for (int mc = 0; mc < 4; mc++) {
            const int m = m0 + (mc << 4) + lr;
            const bool ok = (m >= 0) && (m < RTOT);
            float4 wv = ok ? *(const float4*)(band + (size_t)m * BANDW + coff + lc)
                           : make_float4(0.f, 0.f, 0.f, 0.f);
            float4 vv = ok ? *(const float4*)(V + (size_t)m * DIM + d0 + lc)
                           : make_float4(0.f, 0.f, 0.f, 0.f);
            __syncthreads();
            *(float4*)&Ws[lr][lc] = wv;
            *(float4*)&Vs[lr][lc] = vv;
            __syncthreads();
#pragma unroll
            for (int k = 0; k < 16; k++) {
                float4 a4 = *(const float4*)&Ws[k][ty << 2];
                float4 b4 = *(const float4*)&Vs[k][tx << 2];
                float a[4] = {a4.x, a4.y, a4.z, a4.w};
                float b[4] = {b4.x, b4.y, b4.z, b4.w};
#pragma unroll
                for (int i = 0; i < 4; i++)
#pragma unroll
                    for (int j = 0; j < 4; j++)
                        acc[i][j] = fmaf(a[i], b[j], acc[i][j]);
            }
        }
    }
#pragma unroll
    for (int i = 0; i < 4; i++) {
        const size_t off = (size_t)(n0 + (ty << 2) + i) * DIM + d0 + (tx << 2);
        float4 v = make_float4(acc[i][0], acc[i][1], acc[i][2], acc[i][3]);
        *(float4*)(Y + off) = v;
    }
}

// ---------------------------------------------------------------------------
// ysum[row] += LayerNorm(A[row] + X[row]; g, b)  with ddof=1, eps on std.
// One block per row, 256 threads x 4 contiguous elements.
// ---------------------------------------------------------------------------
__global__ void addln_acc(const float* __restrict__ A, const float* __restrict__ X,
                          const float* __restrict__ g, const float* __restrict__ bb,
                          float* __restrict__ ysum)
{
    __shared__ float red[256];
    const int row = blockIdx.x, tid = threadIdx.x;
    const size_t base = (size_t)row * DIM + tid * 4;
    float4 a = *(const float4*)(A + base);
    float4 x = *(const float4*)(X + base);
    float v0 = a.x + x.x, v1 = a.y + x.y, v2 = a.z + x.z, v3 = a.w + x.w;

    red[tid] = v0 + v1 + v2 + v3;
    __syncthreads();
    for (int s = 128; s > 0; s >>= 1) { if (tid < s) red[tid] += red[tid + s]; __syncthreads(); }
    const float mean = red[0] * (1.f / DIM);
    __syncthreads();

    const float d0 = v0 - mean, d1 = v1 - mean, d2 = v2 - mean, d3 = v3 - mean;
    red[tid] = d0 * d0 + d1 * d1 + d2 * d2 + d3 * d3;
    __syncthreads();
    for (int s = 128; s > 0; s >>= 1) { if (tid < s) red[tid] += red[tid + s]; __syncthreads(); }
    const float scale = 1.f / (sqrtf(red[0] * (1.f / (DIM - 1))) + LN_EPS);

    const int c = tid * 4;
    float4 gg = *(const float4*)(g + c);
    float4 bv = *(const float4*)(bb + c);
    float4 ys = *(float4*)(ysum + base);
    ys.x += gg.x * d0 * scale + bv.x;
    ys.y += gg.y * d1 * scale + bv.y;
    ys.z += gg.z * d2 * scale + bv.z;
    ys.w += gg.w * d3 * scale + bv.w;
    *(float4*)(ysum + base) = ys;
}

// out[row] = LayerNorm(H[row]; g, b), same conventions.
__global__ void ln_only(const float* __restrict__ H,
                        const float* __restrict__ g, const float* __restrict__ bb,
                        float* __restrict__ out)
{
    __shared__ float red[256];
    const int row = blockIdx.x, tid = threadIdx.x;
    const size_t base = (size_t)row * DIM + tid * 4;
    float4 h = *(const float4*)(H + base);
    red[tid] = h.x + h.y + h.z + h.w;
    __syncthreads();
    for (int s = 128; s > 0; s >>= 1) { if (tid < s) red[tid] += red[tid + s]; __syncthreads(); }
    const float mean = red[0] * (1.f / DIM);
    __syncthreads();

    const float d0 = h.x - mean, d1 = h.y - mean, d2 = h.z - mean, d3 = h.w - mean;
    red[tid] = d0 * d0 + d1 * d1 + d2 * d2 + d3 * d3;
    __syncthreads();
    for (int s = 128; s > 0; s >>= 1) { if (tid < s) red[tid] += red[tid + s]; __syncthreads(); }
    const float scale = 1.f / (sqrtf(red[0] * (1.f / (DIM - 1))) + LN_EPS);

    const int c = tid * 4;
    float4 gg = *(const float4*)(g + c);
    float4 bv = *(const float4*)(bb + c);
    float4 o;
    o.x = gg.x * d0 * scale + bv.x;
    o.y = gg.y * d1 * scale + bv.y;
    o.z = gg.z * d2 * scale + bv.z;
    o.w = gg.w * d3 * scale + bv.w;
    *(float4*)(out + base) = o;
}

// out[row] = H[row] . w + bias[0]
__global__ void kd_dot(const float* __restrict__ H, const float* __restrict__ w,
                       const float* __restrict__ bias, float* __restrict__ out)
{
    __shared__ float red[256];
    const int row = blockIdx.x, tid = threadIdx.x;
    float4 h = *(const float4*)(H + (size_t)row * DIM + tid * 4);
    float4 ww = *(const float4*)(w + tid * 4);
    red[tid] = h.x * ww.x + h.y * ww.y + h.z * ww.z + h.w * ww.w;
    __syncthreads();
    for (int s = 128; s > 0; s >>= 1) { if (tid < s) red[tid] += red[tid + s]; __syncthreads(); }
    if (tid == 0) out[row] = red[0] + bias[0];
}

// ---------------------------------------------------------------------------
extern "C" void kernel_launch(void* const* d_in, const int* in_sizes, int n_in,
                              void* d_out, int out_size)
{
    (void)in_sizes; (void)n_in; (void)out_size;

    const float* x1   = (const float*)d_in[0];
    const float* x2   = (const float*)d_in[1];
    const float* x3   = (const float*)d_in[2];
    const float* Wk   = (const float*)d_in[3];
    const float* Wq   = (const float*)d_in[4];
    const float* Wv   = (const float*)d_in[5];
    const float* Wo   = (const float*)d_in[6];
    const float* ka_w = (const float*)d_in[7];
    const float* ka_b = (const float*)d_in[8];
    const float* kb_w = (const float*)d_in[9];
    const float* kb_b = (const float*)d_in[10];
    const float* kc_w = (const float*)d_in[11];
    const float* kc_b = (const float*)d_in[12];
    const float* kd_w = (const float*)d_in[13];
    const float* kd_b = (const float*)d_in[14];
    const float* g1   = (const float*)d_in[15];
    const float* b1   = (const float*)d_in[16];
    const float* g2   = (const float*)d_in[17];
    const float* b2   = (const float*)d_in[18];
    float* out = (float*)d_out;

    float* scratch = nullptr;
    cudaGetSymbolAddress((void**)&scratch, g_scratch);
    float* bK   = scratch + 0 * (size_t)RD;
    float* bQ   = scratch + 1 * (size_t)RD;
    float* bV   = scratch + 2 * (size_t)RD;
    float* bA   = scratch + 3 * (size_t)RD;
    float* ySum = scratch + 4 * (size_t)RD;
    float* band = scratch + 5 * (size_t)RD;

    const dim3 gG(DIM / 128, RTOT / 128);     // (8, 64)
    const dim3 gL(10, RTOT / 64);             // logits: 10 col-blocks x 128 row-blocks
    const dim3 gA(DIM / 64, RTOT / 64);       // apply: 16 d-tiles x 128 n-blocks

    cudaMemsetAsync(ySum, 0, sizeof(float) * (size_t)RD);

    const float* xs[3] = {x1, x2, x3};
    for (int t = 0; t < 3; t++) {
        const float* x = xs[t];
        sgemm128<<<gG, 256>>>(x, Wk, nullptr, bK, DIM, DIM, 1.0f, 0);
        sgemm128<<<gG, 256>>>(x, Wq, nullptr, bQ, DIM, DIM, 0.06f, 0);   // Q_SCALE
        sgemm128<<<gG, 256>>>(x, Wv, nullptr, bV, DIM, DIM, 1.0f, 0);
        band_logits<<<gL, 256>>>(bQ, bK, band);
        band_softmax<<<RTOT, 256>>>(band);
        band_apply<<<gA, 256>>>(band, bV, bA);
        sgemm128<<<gG, 256>>>(bA, Wo, nullptr, bK, DIM, DIM, 1.0f, 0);   // bK = attn out
        addln_acc<<<RTOT, 256>>>(bK, x, g1, b1, ySum);
    }

    sgemm128<<<gG, 256>>>(ySum, ka_w, ka_b, bQ, DIM, DIM, 1.0f, 0);
    sgemm128<<<gG, 256>>>(bQ, kb_w, kb_b, bV, DIM, DIM, 1.0f, 0);
    sgemm128<<<gG, 256>>>(bV, kc_w, kc_b, bQ, DIM, DIM, 1.0f, 1);        // + ReLU
    ln_only<<<RTOT, 256>>>(bQ, g2, b2, bV);
    kd_dot<<<RTOT, 256>>>(bV, kd_w, kd_b, out);
}

// round 4
// speedup vs baseline: 2.0730x; 2.0730x over previous
#include <cuda_runtime.h>
#include <cuda_bf16.h>
#include <cstdint>
#include <math.h>

#define RTOT  8192              // B*N rows
#define SEQ   4096              // per-batch sequence length
#define DIM   1024
#define BANDW 640               // padded band width per row-block
#define LN_EPS 1e-6f
#define RD (RTOT * DIM)

// Scratch layout (floats): K, Q, V, A, ySum, band
__device__ float g_scratch[5 * RD + (size_t)RTOT * BANDW];

// ============================================================================
// mma.sync helpers (base-target PTX, works at .target sm_103)
// ============================================================================
__device__ __forceinline__ unsigned int smem_to_u32(const void* p) {
    unsigned int a;
    asm("{ .reg .u64 t; cvta.to.shared.u64 t, %1; cvt.u32.u64 %0, t; }"
        : "=r"(a) : "l"(p));
    return a;
}

__device__ __forceinline__ void ldsm4(unsigned int& r0, unsigned int& r1,
                                      unsigned int& r2, unsigned int& r3,
                                      unsigned int addr) {
    asm volatile("ldmatrix.sync.aligned.m8n8.x4.shared.b16 {%0,%1,%2,%3}, [%4];"
                 : "=r"(r0), "=r"(r1), "=r"(r2), "=r"(r3) : "r"(addr));
}

__device__ __forceinline__ void mma16816(float* c, unsigned int a0, unsigned int a1,
                                         unsigned int a2, unsigned int a3,
                                         unsigned int b0, unsigned int b1) {
    asm volatile(
        "mma.sync.aligned.m16n8k16.row.col.f32.bf16.bf16.f32 "
        "{%0,%1,%2,%3}, {%4,%5,%6,%7}, {%8,%9}, {%0,%1,%2,%3};"
        : "+f"(c[0]), "+f"(c[1]), "+f"(c[2]), "+f"(c[3])
        : "r"(a0), "r"(a1), "r"(a2), "r"(a3), "r"(b0), "r"(b1));
}

__device__ __forceinline__ unsigned short bfu(float f) {
    return __bfloat16_as_ushort(__float2bfloat16(f));
}
__device__ __forceinline__ float bff(unsigned short u) {
    return __bfloat162float(__ushort_as_bfloat16(u));
}

// split fp32 -> (hi, lo) bf16 pair, packed as uint2 (4 values each)
__device__ __forceinline__ void split4(float4 v, uint2& uh, uint2& ul) {
    unsigned short hx = bfu(v.x), hy = bfu(v.y), hz = bfu(v.z), hw = bfu(v.w);
    uh = make_uint2((unsigned int)hx | ((unsigned int)hy << 16),
                    (unsigned int)hz | ((unsigned int)hw << 16));
    unsigned short lx = bfu(v.x - bff(hx)), ly = bfu(v.y - bff(hy));
    unsigned short lz = bfu(v.z - bff(hz)), lw = bfu(v.w - bff(hw));
    ul = make_uint2((unsigned int)lx | ((unsigned int)ly << 16),
                    (unsigned int)lz | ((unsigned int)lw << 16));
}

// ============================================================================
// Tensor-core GEMM via mma.sync: C[M,Nn] = alpha*(A[M,1024] @ B[Nn,1024]^T)
//   (+bias)(+relu).  fp32 in/out; bf16-split (AhiBhi+AhiBlo+AloBhi), fp32 acc.
// CTA 128x128, BK=64, 8 warps each 32(M)x64(N).
// smem: 4 tiles of [128][72] bf16 (pad 72 -> conflict-free ldmatrix).
// ============================================================================
#define BK   64
#define PADR 72                          // bf16 units per smem row
#define TILE_B (128 * PADR * 2)          // 18432 bytes per tile
#define OFF_AHI 0
#define OFF_ALO (1 * TILE_B)
#define OFF_BHI (2 * TILE_B)
#define OFF_BLO (3 * TILE_B)
#define SMT     (4 * TILE_B)             // 73728 bytes

__global__ void __launch_bounds__(256, 2)
tgemm(const float* __restrict__ A, const float* __restrict__ B,
      const float* __restrict__ bias, float* __restrict__ C,
      int Nn, float alpha, int relu)
{
    extern __shared__ __align__(16) char smc[];
    const unsigned int sbase = smem_to_u32(smc);
    const int tid = threadIdx.x;
    const int lane = tid & 31;
    const int wid = tid >> 5;
    const int wm = wid & 3;              // 4 warps over M (32 rows each)
    const int wn = wid >> 2;             // 2 warps over N (64 cols each)
    const int m0 = blockIdx.y << 7;
    const int n0 = blockIdx.x << 7;

    float acc[2][8][4];
#pragma unroll
    for (int i = 0; i < 2; i++)
#pragma unroll
        for (int j = 0; j < 8; j++)
#pragma unroll
            for (int c = 0; c < 4; c++) acc[i][j][c] = 0.f;

    const int lrow = tid >> 2;           // 0..63
    const int lseg = (tid & 3) << 2;     // float4 index base (0,4,8,12)

    // ldmatrix source addresses (byte offsets into a [128][PADR] bf16 tile)
    const unsigned int a_off =
        (unsigned int)((wm * 32 + (lane & 15)) * PADR + ((lane >> 4) << 3)) * 2;
    const unsigned int b_off =
        (unsigned int)((wn * 64 + (lane & 7) + ((lane >> 4) << 3)) * PADR +
                       (((lane >> 3) & 1) << 3)) * 2;

    for (int kc = 0; kc < DIM / BK; kc++) {
        const int k0 = kc * BK;
        __syncthreads();
        // ---- load + split A and B chunks into smem ----
#pragma unroll
        for (int half = 0; half < 2; half++) {
            const int r = lrow + half * 64;
            const float4* ap = (const float4*)(A + (size_t)(m0 + r) * DIM + k0);
            const float4* bp = (const float4*)(B + (size_t)(n0 + r) * DIM + k0);
#pragma unroll
            for (int j = 0; j < 4; j++) {
                const int q = lseg + j;          // float4 index 0..15
                uint2 uh, ul;
                split4(ap[q], uh, ul);
                const int so = (r * PADR + q * 4) * 2;
                *(uint2*)(smc + OFF_AHI + so) = uh;
                *(uint2*)(smc + OFF_ALO + so) = ul;
                split4(bp[q], uh, ul);
                *(uint2*)(smc + OFF_BHI + so) = uh;
                *(uint2*)(smc + OFF_BLO + so) = ul;
            }
        }
        __syncthreads();
        // ---- mma over 4 k-steps of 16 ----
#pragma unroll
        for (int ks = 0; ks < 4; ks++) {
            const unsigned int kb = (unsigned int)(ks * 16) * 2;
            unsigned int ahi[2][4], alo[2][4];
#pragma unroll
            for (int mt = 0; mt < 2; mt++) {
                const unsigned int ad = sbase + (unsigned int)(mt * 16 * PADR * 2) + a_off + kb;
                ldsm4(ahi[mt][0], ahi[mt][1], ahi[mt][2], ahi[mt][3], ad + OFF_AHI);
                ldsm4(alo[mt][0], alo[mt][1], alo[mt][2], alo[mt][3], ad + OFF_ALO);
            }
            unsigned int bhi[8][2], blo[8][2];
#pragma unroll
            for (int np = 0; np < 4; np++) {
                const unsigned int bd = sbase + (unsigned int)(np * 16 * PADR * 2) + b_off + kb;
                unsigned int r0, r1, r2, r3;
                ldsm4(r0, r1, r2, r3, bd + OFF_BHI);
                bhi[2*np][0] = r0; bhi[2*np][1] = r1;
                bhi[2*np+1][0] = r2; bhi[2*np+1][1] = r3;
                ldsm4(r0, r1, r2, r3, bd + OFF_BLO);
                blo[2*np][0] = r0; blo[2*np][1] = r1;
                blo[2*np+1][0] = r2; blo[2*np+1][1] = r3;
            }
#pragma unroll
            for (int mt = 0; mt < 2; mt++)
#pragma unroll
                for (int nt = 0; nt < 8; nt++) {
                    mma16816(acc[mt][nt], ahi[mt][0], ahi[mt][1], ahi[mt][2], ahi[mt][3],
                             bhi[nt][0], bhi[nt][1]);
                    mma16816(acc[mt][nt], ahi[mt][0], ahi[mt][1], ahi[mt][2], ahi[mt][3],
                             blo[nt][0], blo[nt][1]);
                    mma16816(acc[mt][nt], alo[mt][0], alo[mt][1], alo[mt][2], alo[mt][3],
                             bhi[nt][0], bhi[nt][1]);
                }
        }
    }

    // ---- epilogue ----
    const int group = lane >> 2, tig = lane & 3;
#pragma unroll
    for (int mt = 0; mt < 2; mt++)
#pragma unroll
        for (int nt = 0; nt < 8; nt++) {
            const int col = n0 + wn * 64 + nt * 8 + tig * 2;
            float bx = 0.f, by = 0.f;
            if (bias) { bx = bias[col]; by = bias[col + 1]; }
#pragma unroll
            for (int h = 0; h < 2; h++) {
                const int row = m0 + wm * 32 + mt * 16 + group + h * 8;
                float v0 = alpha * acc[mt][nt][2 * h] + bx;
                float v1 = alpha * acc[mt][nt][2 * h + 1] + by;
                if (relu) { v0 = fmaxf(v0, 0.f); v1 = fmaxf(v1, 0.f); }
                *(float2*)(C + (size_t)row * Nn + col) = make_float2(v0, v1);
            }
        }
}

// ---------------------------------------------------------------------------
// Band logits: band[i][c] = Q[i] . K[i&~63 - 256 + c], c in [0,640)
// ---------------------------------------------------------------------------
__global__ void __launch_bounds__(256)
band_logits(const float* __restrict__ Q, const float* __restrict__ Kk,
            float* __restrict__ band)
{
    __shared__ float Qs[16][64];
    __shared__ float Ks[16][64];
    const int rb = blockIdx.y, cb = blockIdx.x;
    const int i0 = rb << 6;
    const int j0 = i0 - 256 + (cb << 6);
    const int tid = threadIdx.x;
    const int lr = tid >> 2;
    const int ls = (tid & 3) << 2;
    const int tx = tid & 15, ty = tid >> 4;

    const float* Qp = Q + (size_t)(i0 + lr) * DIM + ls;
    const int jrow = j0 + lr;
    const bool kok = (jrow >= 0) && (jrow < RTOT);
    const float* Kp = Kk + (size_t)(kok ? jrow : 0) * DIM + ls;

    float acc[4][4] = {};
    for (int k0 = 0; k0 < DIM; k0 += 16) {
        float4 qv = *(const float4*)(Qp + k0);
        float4 kv = kok ? *(const float4*)(Kp + k0) : make_float4(0.f, 0.f, 0.f, 0.f);
        __syncthreads();
        Qs[ls + 0][lr] = qv.x; Qs[ls + 1][lr] = qv.y;
        Qs[ls + 2][lr] = qv.z; Qs[ls + 3][lr] = qv.w;
        Ks[ls + 0][lr] = kv.x; Ks[ls + 1][lr] = kv.y;
        Ks[ls + 2][lr] = kv.z; Ks[ls + 3][lr] = kv.w;
        __syncthreads();
#pragma unroll
        for (int k = 0; k < 16; k++) {
            float4 a4 = *(const float4*)&Qs[k][ty << 2];
            float4 b4 = *(const float4*)&Ks[k][tx << 2];
            float a[4] = {a4.x, a4.y, a4.z, a4.w};
            float b[4] = {b4.x, b4.y, b4.z, b4.w};
#pragma unroll
            for (int i = 0; i < 4; i++)
#pragma unroll
                for (int j = 0; j < 4; j++)
                    acc[i][j] = fmaf(a[i], b[j], acc[i][j]);
        }
    }
#pragma unroll
    for (int i = 0; i < 4; i++) {
        const size_t off = (size_t)(i0 + (ty << 2) + i) * BANDW + (cb << 6) + (tx << 2);
        *(float4*)(band + off) = make_float4(acc[i][0], acc[i][1], acc[i][2], acc[i][3]);
    }
}

// ---------------------------------------------------------------------------
__global__ void band_softmax(float* __restrict__ band)
{
    __shared__ float red[256];
    const int i = blockIdx.x;
    const int tid = threadIdx.x;
    const int i0 = i & ~63;
    const int jstart = i0 - 256;
    const int bs = (i < SEQ) ? 0 : SEQ;
    const int jmin = max(i - 255, bs);
    const int jmax = min(i + 255, bs + SEQ - 1);
    const int cmin = jmin - jstart, cmax = jmax - jstart;
    float* row = band + (size_t)i * BANDW;

    float m = -1e30f;
    for (int c = tid; c < BANDW; c += 256)
        if (c >= cmin && c <= cmax) m = fmaxf(m, row[c]);
    red[tid] = m; __syncthreads();
    for (int s = 128; s > 0; s >>= 1) {
        if (tid < s) red[tid] = fmaxf(red[tid], red[tid + s]);
        __syncthreads();
    }
    m = red[0]; __syncthreads();

    float ssum = 0.f;
    for (int c = tid; c < BANDW; c += 256)
        if (c >= cmin && c <= cmax) ssum += __expf(row[c] - m);
    red[tid] = ssum; __syncthreads();
    for (int s = 128; s > 0; s >>= 1) {
        if (tid < s) red[tid] += red[tid + s];
        __syncthreads();
    }
    const float inv = 1.f / red[0];

    for (int c = tid; c < BANDW; c += 256) {
        float v = (c >= cmin && c <= cmax) ? __expf(row[c] - m) * inv : 0.f;
        row[c] = v;
    }
}

// ---------------------------------------------------------------------------
__global__ void __launch_bounds__(256)
band_apply(const float* __restrict__ band, const float* __restrict__ V,
           float* __restrict__ Y)
{
    __shared__ float Ws[16][64];
    __shared__ float Vs[16][64];
    const int nb = blockIdx.y, dt = blockIdx.x;
    const int n0 = nb << 6, d0 = dt << 6;
    const int tid = threadIdx.x;
    const int lr = tid >> 4;
    const int lc = (tid & 15) << 2;
    const int tx = tid & 15, ty = tid >> 4;

    float acc[4][4] = {};
    for (int cb = 0; cb < 9; cb++) {
        const int m0 = n0 - 256 + (cb << 6);
        const int coff = 512 - (cb << 6);
        for (int mc = 0; mc < 4; mc++) {
            const int m = m0 + (mc << 4) + lr;
            const bool ok = (m >= 0) && (m < RTOT);
            float4 wv = ok ? *(const float4*)(band + (size_t)m * BANDW + coff + lc)
                           : make_float4(0.f, 0.f, 0.f, 0.f);
            float4 vv = ok ? *(const float4*)(V + (size_t)m * DIM + d0 + lc)
                           : make_float4(0.f, 0.f, 0.f, 0.f);
            __syncthreads();
            *(float4*)&Ws[lr][lc] = wv;
            *(float4*)&Vs[lr][lc] = vv;
            __syncthreads();
#pragma unroll
            for (int k = 0; k < 16; k++) {
                float4 a4 = *(const float4*)&Ws[k][ty << 2];
                float4 b4 = *(const float4*)&Vs[k][tx << 2];
                float a[4] = {a4.x, a4.y, a4.z, a4.w};
                float b[4] = {b4.x, b4.y, b4.z, b4.w};
#pragma unroll
                for (int i = 0; i < 4; i++)
#pragma unroll
                    for (int j = 0; j < 4; j++)
                        acc[i][j] = fmaf(a[i], b[j], acc[i][j]);
            }
        }
    }
#pragma unroll
    for (int i = 0; i < 4; i++) {
        const size_t off = (size_t)(n0 + (ty << 2) + i) * DIM + d0 + (tx << 2);
        *(float4*)(Y + off) = make_float4(acc[i][0], acc[i][1], acc[i][2], acc[i][3]);
    }
}

// ---------------------------------------------------------------------------
__global__ void addln_acc(const float* __restrict__ A, const float* __restrict__ X,
                          const float* __restrict__ g, const float* __restrict__ bb,
                          float* __restrict__ ysum)
{
    __shared__ float red[256];
    const int row = blockIdx.x, tid = threadIdx.x;
    const size_t base = (size_t)row * DIM + tid * 4;
    float4 a = *(const float4*)(A + base);
    float4 x = *(const float4*)(X + base);
    float v0 = a.x + x.x, v1 = a.y + x.y, v2 = a.z + x.z, v3 = a.w + x.w;

    red[tid] = v0 + v1 + v2 + v3;
    __syncthreads();
    for (int s = 128; s > 0; s >>= 1) { if (tid < s) red[tid] += red[tid + s]; __syncthreads(); }
    const float mean = red[0] * (1.f / DIM);
    __syncthreads();

    const float d0 = v0 - mean, d1 = v1 - mean, d2 = v2 - mean, d3 = v3 - mean;
    red[tid] = d0 * d0 + d1 * d1 + d2 * d2 + d3 * d3;
    __syncthreads();
    for (int s = 128; s > 0; s >>= 1) { if (tid < s) red[tid] += red[tid + s]; __syncthreads(); }
    const float scale = 1.f / (sqrtf(red[0] * (1.f / (DIM - 1))) + LN_EPS);

    const int c = tid * 4;
    float4 gg = *(const float4*)(g + c);
    float4 bv = *(const float4*)(bb + c);
    float4 ys = *(float4*)(ysum + base);
    ys.x += gg.x * d0 * scale + bv.x;
    ys.y += gg.y * d1 * scale + bv.y;
    ys.z += gg.z * d2 * scale + bv.z;
    ys.w += gg.w * d3 * scale + bv.w;
    *(float4*)(ysum + base) = ys;
}

__global__ void ln_only(const float* __restrict__ H,
                        const float* __restrict__ g, const float* __restrict__ bb,
                        float* __restrict__ out)
{
    __shared__ float red[256];
    const int row = blockIdx.x, tid = threadIdx.x;
    const size_t base = (size_t)row * DIM + tid * 4;
    float4 h = *(const float4*)(H + base);
    red[tid] = h.x + h.y + h.z + h.w;
    __syncthreads();
    for (int s = 128; s > 0; s >>= 1) { if (tid < s) red[tid] += red[tid + s]; __syncthreads(); }
    const float mean = red[0] * (1.f / DIM);
    __syncthreads();

    const float d0 = h.x - mean, d1 = h.y - mean, d2 = h.z - mean, d3 = h.w - mean;
    red[tid] = d0 * d0 + d1 * d1 + d2 * d2 + d3 * d3;
    __syncthreads();
    for (int s = 128; s > 0; s >>= 1) { if (tid < s) red[tid] += red[tid + s]; __syncthreads(); }
    const float scale = 1.f / (sqrtf(red[0] * (1.f / (DIM - 1))) + LN_EPS);

    const int c = tid * 4;
    float4 gg = *(const float4*)(g + c);
    float4 bv = *(const float4*)(bb + c);
    float4 o;
    o.x = gg.x * d0 * scale + bv.x;
    o.y = gg.y * d1 * scale + bv.y;
    o.z = gg.z * d2 * scale + bv.z;
    o.w = gg.w * d3 * scale + bv.w;
    *(float4*)(out + base) = o;
}

__global__ void kd_dot(const float* __restrict__ H, const float* __restrict__ w,
                       const float* __restrict__ bias, float* __restrict__ out)
{
    __shared__ float red[256];
    const int row = blockIdx.x, tid = threadIdx.x;
    float4 h = *(const float4*)(H + (size_t)row * DIM + tid * 4);
    float4 ww = *(const float4*)(w + tid * 4);
    red[tid] = h.x * ww.x + h.y * ww.y + h.z * ww.z + h.w * ww.w;
    __syncthreads();
    for (int s = 128; s > 0; s >>= 1) { if (tid < s) red[tid] += red[tid + s]; __syncthreads(); }
    if (tid == 0) out[row] = red[0] + bias[0];
}

// ---------------------------------------------------------------------------
extern "C" void kernel_launch(void* const* d_in, const int* in_sizes, int n_in,
                              void* d_out, int out_size)
{
    (void)in_sizes; (void)n_in; (void)out_size;

    const float* x1   = (const float*)d_in[0];
    const float* x2   = (const float*)d_in[1];
    const float* x3   = (const float*)d_in[2];
    const float* Wk   = (const float*)d_in[3];
    const float* Wq   = (const float*)d_in[4];
    const float* Wv   = (const float*)d_in[5];
    const float* Wo   = (const float*)d_in[6];
    const float* ka_w = (const float*)d_in[7];
    const float* ka_b = (const float*)d_in[8];
    const float* kb_w = (const float*)d_in[9];
    const float* kb_b = (const float*)d_in[10];
    const float* kc_w = (const float*)d_in[11];
    const float* kc_b = (const float*)d_in[12];
    const float* kd_w = (const float*)d_in[13];
    const float* kd_b = (const float*)d_in[14];
    const float* g1   = (const float*)d_in[15];
    const float* b1   = (const float*)d_in[16];
    const float* g2   = (const float*)d_in[17];
    const float* b2   = (const float*)d_in[18];
    float* out = (float*)d_out;

    float* scratch = nullptr;
    cudaGetSymbolAddress((void**)&scratch, g_scratch);
    float* bK   = scratch + 0 * (size_t)RD;
    float* bQ   = scratch + 1 * (size_t)RD;
    float* bV   = scratch + 2 * (size_t)RD;
    float* bA   = scratch + 3 * (size_t)RD;
    float* ySum = scratch + 4 * (size_t)RD;
    float* band = scratch + 5 * (size_t)RD;

    cudaFuncSetAttribute(tgemm, cudaFuncAttributeMaxDynamicSharedMemorySize, SMT);

    const dim3 gT(DIM / 128, RTOT / 128);     // (8, 64)
    const dim3 gL(10, RTOT / 64);
    const dim3 gA(DIM / 64, RTOT / 64);

    cudaMemsetAsync(ySum, 0, sizeof(float) * (size_t)RD);

    const float* xs[3] = {x1, x2, x3};
    for (int t = 0; t < 3; t++) {
        const float* x = xs[t];
        tgemm<<<gT, 256, SMT>>>(x, Wk, nullptr, bK, DIM, 1.0f, 0);
        tgemm<<<gT, 256, SMT>>>(x, Wq, nullptr, bQ, DIM, 0.06f, 0);   // Q_SCALE
        tgemm<<<gT, 256, SMT>>>(x, Wv, nullptr, bV, DIM, 1.0f, 0);
        band_logits<<<gL, 256>>>(bQ, bK, band);
        band_softmax<<<RTOT, 256>>>(band);
        band_apply<<<gA, 256>>>(band, bV, bA);
        tgemm<<<gT, 256, SMT>>>(bA, Wo, nullptr, bK, DIM, 1.0f, 0);
        addln_acc<<<RTOT, 256>>>(bK, x, g1, b1, ySum);
    }

    tgemm<<<gT, 256, SMT>>>(ySum, ka_w, ka_b, bQ, DIM, 1.0f, 0);
    tgemm<<<gT, 256, SMT>>>(bQ, kb_w, kb_b, bV, DIM, 1.0f, 0);
    tgemm<<<gT, 256, SMT>>>(bV, kc_w, kc_b, bQ, DIM, 1.0f, 1);       // + ReLU
    ln_only<<<RTOT, 256>>>(bQ, g2, b2, bV);
    kd_dot<<<RTOT, 256>>>(bV, kd_w, kd_b, out);
}

// round 5
// speedup vs baseline: 2.3546x; 1.1358x over previous
#include <cuda_runtime.h>
#include <cuda_bf16.h>
#include <cstdint>
#include <math.h>

#define RTOT  8192              // B*N rows
#define SEQ   4096              // per-batch sequence length
#define DIM   1024
#define BANDW 640               // padded band width per row-block
#define LN_EPS 1e-6f
#define RD (RTOT * DIM)

// Scratch layout (floats): K, Q, V, A, ySum, band
__device__ float g_scratch[5 * RD + (size_t)RTOT * BANDW];

// ============================================================================
// mma.sync helpers (base-target PTX)
// ============================================================================
__device__ __forceinline__ unsigned int smem_to_u32(const void* p) {
    unsigned int a;
    asm("{ .reg .u64 t; cvta.to.shared.u64 t, %1; cvt.u32.u64 %0, t; }"
        : "=r"(a) : "l"(p));
    return a;
}

__device__ __forceinline__ void ldsm4(unsigned int& r0, unsigned int& r1,
                                      unsigned int& r2, unsigned int& r3,
                                      unsigned int addr) {
    asm volatile("ldmatrix.sync.aligned.m8n8.x4.shared.b16 {%0,%1,%2,%3}, [%4];"
                 : "=r"(r0), "=r"(r1), "=r"(r2), "=r"(r3) : "r"(addr));
}
__device__ __forceinline__ void ldsm4t(unsigned int& r0, unsigned int& r1,
                                       unsigned int& r2, unsigned int& r3,
                                       unsigned int addr) {
    asm volatile("ldmatrix.sync.aligned.m8n8.x4.trans.shared.b16 {%0,%1,%2,%3}, [%4];"
                 : "=r"(r0), "=r"(r1), "=r"(r2), "=r"(r3) : "r"(addr));
}

__device__ __forceinline__ void mma16816(float* c, unsigned int a0, unsigned int a1,
                                         unsigned int a2, unsigned int a3,
                                         unsigned int b0, unsigned int b1) {
    asm volatile(
        "mma.sync.aligned.m16n8k16.row.col.f32.bf16.bf16.f32 "
        "{%0,%1,%2,%3}, {%4,%5,%6,%7}, {%8,%9}, {%0,%1,%2,%3};"
        : "+f"(c[0]), "+f"(c[1]), "+f"(c[2]), "+f"(c[3])
        : "r"(a0), "r"(a1), "r"(a2), "r"(a3), "r"(b0), "r"(b1));
}

__device__ __forceinline__ unsigned short bfu(float f) {
    return __bfloat16_as_ushort(__float2bfloat16(f));
}
__device__ __forceinline__ float bff(unsigned short u) {
    return __bfloat162float(__ushort_as_bfloat16(u));
}

// split fp32x4 -> packed hi/lo bf16 (uint2 each)
__device__ __forceinline__ void split4(float4 v, uint2& uh, uint2& ul) {
    unsigned short hx = bfu(v.x), hy = bfu(v.y), hz = bfu(v.z), hw = bfu(v.w);
    uh = make_uint2((unsigned int)hx | ((unsigned int)hy << 16),
                    (unsigned int)hz | ((unsigned int)hw << 16));
    unsigned short lx = bfu(v.x - bff(hx)), ly = bfu(v.y - bff(hy));
    unsigned short lz = bfu(v.z - bff(hz)), lw = bfu(v.w - bff(hw));
    ul = make_uint2((unsigned int)lx | ((unsigned int)ly << 16),
                    (unsigned int)lz | ((unsigned int)lw << 16));
}

// ============================================================================
// tgemm: C[M,Nn] = alpha*(A[M,1024] @ B[Nn,1024]^T) (+bias)(+relu)
// bf16-split-3, CTA 128x128, BK=64, 8 warps (4M x 2N).
// ============================================================================
#define PADR 72
#define TILE_B (128 * PADR * 2)
#define OFF_AHI 0
#define OFF_ALO (1 * TILE_B)
#define OFF_BHI (2 * TILE_B)
#define OFF_BLO (3 * TILE_B)
#define SMT     (4 * TILE_B)

__global__ void __launch_bounds__(256, 2)
tgemm(const float* __restrict__ A, const float* __restrict__ B,
      const float* __restrict__ bias, float* __restrict__ C,
      int Nn, float alpha, int relu)
{
    extern __shared__ __align__(16) char smc[];
    const unsigned int sbase = smem_to_u32(smc);
    const int tid = threadIdx.x;
    const int lane = tid & 31;
    const int wid = tid >> 5;
    const int wm = wid & 3;
    const int wn = wid >> 2;
    const int m0 = blockIdx.y << 7;
    const int n0 = blockIdx.x << 7;

    float acc[2][8][4];
#pragma unroll
    for (int i = 0; i < 2; i++)
#pragma unroll
        for (int j = 0; j < 8; j++)
#pragma unroll
            for (int c = 0; c < 4; c++) acc[i][j][c] = 0.f;

    const int lrow = tid >> 2;
    const int lseg = (tid & 3) << 2;

    const unsigned int a_off =
        (unsigned int)((wm * 32 + (lane & 15)) * PADR + ((lane >> 4) << 3)) * 2;
    const unsigned int b_off =
        (unsigned int)((wn * 64 + (lane & 7) + ((lane >> 4) << 3)) * PADR +
                       (((lane >> 3) & 1) << 3)) * 2;

    for (int kc = 0; kc < DIM / 64; kc++) {
        const int k0 = kc * 64;
        __syncthreads();
#pragma unroll
        for (int half = 0; half < 2; half++) {
            const int r = lrow + half * 64;
            const float4* ap = (const float4*)(A + (size_t)(m0 + r) * DIM + k0);
            const float4* bp = (const float4*)(B + (size_t)(n0 + r) * DIM + k0);
#pragma unroll
            for (int j = 0; j < 4; j++) {
                const int q = lseg + j;
                uint2 uh, ul;
                split4(ap[q], uh, ul);
                const int so = (r * PADR + q * 4) * 2;
                *(uint2*)(smc + OFF_AHI + so) = uh;
                *(uint2*)(smc + OFF_ALO + so) = ul;
                split4(bp[q], uh, ul);
                *(uint2*)(smc + OFF_BHI + so) = uh;
                *(uint2*)(smc + OFF_BLO + so) = ul;
            }
        }
        __syncthreads();
#pragma unroll
        for (int ks = 0; ks < 4; ks++) {
            const unsigned int kb = (unsigned int)(ks * 16) * 2;
            unsigned int ahi[2][4], alo[2][4];
#pragma unroll
            for (int mt = 0; mt < 2; mt++) {
                const unsigned int ad = sbase + (unsigned int)(mt * 16 * PADR * 2) + a_off + kb;
                ldsm4(ahi[mt][0], ahi[mt][1], ahi[mt][2], ahi[mt][3], ad + OFF_AHI);
                ldsm4(alo[mt][0], alo[mt][1], alo[mt][2], alo[mt][3], ad + OFF_ALO);
            }
            unsigned int bhi[8][2], blo[8][2];
#pragma unroll
            for (int np = 0; np < 4; np++) {
                const unsigned int bd = sbase + (unsigned int)(np * 16 * PADR * 2) + b_off + kb;
                unsigned int r0, r1, r2, r3;
                ldsm4(r0, r1, r2, r3, bd + OFF_BHI);
                bhi[2*np][0] = r0; bhi[2*np][1] = r1;
                bhi[2*np+1][0] = r2; bhi[2*np+1][1] = r3;
                ldsm4(r0, r1, r2, r3, bd + OFF_BLO);
                blo[2*np][0] = r0; blo[2*np][1] = r1;
                blo[2*np+1][0] = r2; blo[2*np+1][1] = r3;
            }
#pragma unroll
            for (int mt = 0; mt < 2; mt++)
#pragma unroll
                for (int nt = 0; nt < 8; nt++) {
                    mma16816(acc[mt][nt], ahi[mt][0], ahi[mt][1], ahi[mt][2], ahi[mt][3],
                             bhi[nt][0], bhi[nt][1]);
                    mma16816(acc[mt][nt], ahi[mt][0], ahi[mt][1], ahi[mt][2], ahi[mt][3],
                             blo[nt][0], blo[nt][1]);
                    mma16816(acc[mt][nt], alo[mt][0], alo[mt][1], alo[mt][2], alo[mt][3],
                             bhi[nt][0], bhi[nt][1]);
                }
        }
    }

    const int group = lane >> 2, tig = lane & 3;
#pragma unroll
    for (int mt = 0; mt < 2; mt++)
#pragma unroll
        for (int nt = 0; nt < 8; nt++) {
            const int col = n0 + wn * 64 + nt * 8 + tig * 2;
            float bx = 0.f, by = 0.f;
            if (bias) { bx = bias[col]; by = bias[col + 1]; }
#pragma unroll
            for (int h = 0; h < 2; h++) {
                const int row = m0 + wm * 32 + mt * 16 + group + h * 8;
                float v0 = alpha * acc[mt][nt][2 * h] + bx;
                float v1 = alpha * acc[mt][nt][2 * h + 1] + by;
                if (relu) { v0 = fmaxf(v0, 0.f); v1 = fmaxf(v1, 0.f); }
                *(float2*)(C + (size_t)row * Nn + col) = make_float2(v0, v1);
            }
        }
}

// ============================================================================
// band_logits_mma: band[i0+r][cb*128+c] = Q[i0+r] . K[i0-256+cb*128+c]
// CTA tile 64(M) x 128(N), K=1024, BK=64. 8 warps: wm in {0,1}, wn in {0..3}.
// ============================================================================
#define BL_AHI 0
#define BL_ALO (64 * PADR * 2)
#define BL_BHI (2 * 64 * PADR * 2)
#define BL_BLO (BL_BHI + 128 * PADR * 2)
#define BL_SMT (BL_BLO + 128 * PADR * 2)     // 55296

__global__ void __launch_bounds__(256, 2)
band_logits_mma(const float* __restrict__ Q, const float* __restrict__ Kk,
                float* __restrict__ band)
{
    extern __shared__ __align__(16) char smc[];
    const unsigned int sbase = smem_to_u32(smc);
    const int tid = threadIdx.x;
    const int lane = tid & 31;
    const int wid = tid >> 5;
    const int wm = wid & 1;              // 2 warps over M (32 rows)
    const int wn = wid >> 1;             // 4 warps over N (32 cols)
    const int i0 = blockIdx.y << 6;
    const int j0 = i0 - 256 + (blockIdx.x << 7);

    float acc[2][4][4];
#pragma unroll
    for (int i = 0; i < 2; i++)
#pragma unroll
        for (int j = 0; j < 4; j++)
#pragma unroll
            for (int c = 0; c < 4; c++) acc[i][j][c] = 0.f;

    const unsigned int a_off =
        (unsigned int)((wm * 32 + (lane & 15)) * PADR + ((lane >> 4) << 3)) * 2;
    const unsigned int b_off =
        (unsigned int)((wn * 32 + (lane & 7) + ((lane >> 4) << 3)) * PADR +
                       (((lane >> 3) & 1) << 3)) * 2;

    const int ar = tid >> 2;             // 0..63 A row
    const int aq = (tid & 3) << 2;       // A float4 base
    const int br = tid >> 1;             // 0..127 B row
    const int bq = (tid & 1) << 3;       // B float4 base
    const int jrow = j0 + br;
    const bool bok = (jrow >= 0) && (jrow < RTOT);

    for (int kc = 0; kc < DIM / 64; kc++) {
        const int k0 = kc * 64;
        __syncthreads();
        {
            const float4* ap = (const float4*)(Q + (size_t)(i0 + ar) * DIM + k0);
#pragma unroll
            for (int j = 0; j < 4; j++) {
                const int q = aq + j;
                uint2 uh, ul;
                split4(ap[q], uh, ul);
                const int so = (ar * PADR + q * 4) * 2;
                *(uint2*)(smc + BL_AHI + so) = uh;
                *(uint2*)(smc + BL_ALO + so) = ul;
            }
        }
        {
            const float4* bp = (const float4*)(Kk + (size_t)(bok ? jrow : 0) * DIM + k0);
#pragma unroll
            for (int j = 0; j < 8; j++) {
                const int q = bq + j;
                float4 v = bok ? bp[q] : make_float4(0.f, 0.f, 0.f, 0.f);
                uint2 uh, ul;
                split4(v, uh, ul);
                const int so = (br * PADR + q * 4) * 2;
                *(uint2*)(smc + BL_BHI + so) = uh;
                *(uint2*)(smc + BL_BLO + so) = ul;
            }
        }
        __syncthreads();
#pragma unroll
        for (int ks = 0; ks < 4; ks++) {
            const unsigned int kb = (unsigned int)(ks * 16) * 2;
            unsigned int ahi[2][4], alo[2][4];
#pragma unroll
            for (int mt = 0; mt < 2; mt++) {
                const unsigned int ad = sbase + (unsigned int)(mt * 16 * PADR * 2) + a_off + kb;
                ldsm4(ahi[mt][0], ahi[mt][1], ahi[mt][2], ahi[mt][3], ad + BL_AHI);
                ldsm4(alo[mt][0], alo[mt][1], alo[mt][2], alo[mt][3], ad + BL_ALO);
            }
            unsigned int bhi[4][2], blo[4][2];
#pragma unroll
            for (int np = 0; np < 2; np++) {
                const unsigned int bd = sbase + (unsigned int)(np * 16 * PADR * 2) + b_off + kb;
                unsigned int r0, r1, r2, r3;
                ldsm4(r0, r1, r2, r3, bd + BL_BHI);
                bhi[2*np][0] = r0; bhi[2*np][1] = r1;
                bhi[2*np+1][0] = r2; bhi[2*np+1][1] = r3;
                ldsm4(r0, r1, r2, r3, bd + BL_BLO);
                blo[2*np][0] = r0; blo[2*np][1] = r1;
                blo[2*np+1][0] = r2; blo[2*np+1][1] = r3;
            }
#pragma unroll
            for (int mt = 0; mt < 2; mt++)
#pragma unroll
                for (int nt = 0; nt < 4; nt++) {
                    mma16816(acc[mt][nt], ahi[mt][0], ahi[mt][1], ahi[mt][2], ahi[mt][3],
                             bhi[nt][0], bhi[nt][1]);
                    mma16816(acc[mt][nt], ahi[mt][0], ahi[mt][1], ahi[mt][2], ahi[mt][3],
                             blo[nt][0], blo[nt][1]);
                    mma16816(acc[mt][nt], alo[mt][0], alo[mt][1], alo[mt][2], alo[mt][3],
                             bhi[nt][0], bhi[nt][1]);
                }
        }
    }

    const int group = lane >> 2, tig = lane & 3;
#pragma unroll
    for (int mt = 0; mt < 2; mt++)
#pragma unroll
        for (int nt = 0; nt < 4; nt++) {
            const int col = (blockIdx.x << 7) + wn * 32 + nt * 8 + tig * 2;
#pragma unroll
            for (int h = 0; h < 2; h++) {
                const int row = i0 + wm * 32 + mt * 16 + group + h * 8;
                *(float2*)(band + (size_t)row * BANDW + col) =
                    make_float2(acc[mt][nt][2 * h], acc[mt][nt][2 * h + 1]);
            }
        }
}

// ============================================================================
// band_apply_mma: Y[n,d] = sum_m w[m,n] * V[m,d], m in 9x64 window.
// CTA tile 64(n) x 64(d). A = w^T built transposed in smem; B = V k-major,
// loaded with ldmatrix.trans. 8 warps: wm in {0..3} (16 n-rows), wn in {0,1}.
// ============================================================================
#define BA_AHI 0
#define BA_ALO (64 * PADR * 2)
#define BA_BHI (2 * 64 * PADR * 2)
#define BA_BLO (3 * 64 * PADR * 2)
#define BA_SMT (4 * 64 * PADR * 2)          // 36864

__global__ void __launch_bounds__(256, 2)
band_apply_mma(const float* __restrict__ band, const float* __restrict__ V,
               float* __restrict__ Y)
{
    extern __shared__ __align__(16) char smc[];
    const unsigned int sbase = smem_to_u32(smc);
    const int tid = threadIdx.x;
    const int lane = tid & 31;
    const int wid = tid >> 5;
    const int wm = wid & 3;              // 4 warps over n (16 rows each)
    const int wn = wid >> 2;             // 2 warps over d (32 cols each)
    const int n0 = blockIdx.y << 6;
    const int d0 = blockIdx.x << 6;

    float acc[4][4];
#pragma unroll
    for (int j = 0; j < 4; j++)
#pragma unroll
        for (int c = 0; c < 4; c++) acc[j][c] = 0.f;

    // A fragment (row-major [n][k]) address
    const unsigned int a_off =
        (unsigned int)((wm * 16 + (lane & 15)) * PADR + ((lane >> 4) << 3)) * 2;
    // B fragment via ldmatrix.trans on [k][d] storage:
    // row = kk + (lane&7) + (((lane>>3)&1)<<3), colbyte = (dd + ((lane>>4)<<3))*2
    const int btr = (lane & 7) + (((lane >> 3) & 1) << 3);
    const int btc = (lane >> 4) << 3;

    const int r64 = tid >> 2;            // 0..63
    const int c4 = tid & 3;

    unsigned short* Ahi = (unsigned short*)(smc + BA_AHI);
    unsigned short* Alo = (unsigned short*)(smc + BA_ALO);

    for (int ch = 0; ch < 9; ch++) {
        const int mb = n0 - 256 + (ch << 6);
        const int coff = 512 - (ch << 6);
        const int mrow = mb + r64;
        const bool ok = (mrow >= 0) && (mrow < RTOT);
        __syncthreads();
        // ---- w tile: read band[m][coff + c] (coalesced), store transposed
        //      As[c][m] so A = w^T (row n=c, col k=m) ----
        {
            const float4* wp = (const float4*)(band + (size_t)(ok ? mrow : 0) * BANDW + coff);
#pragma unroll
            for (int j = 0; j < 4; j++) {
                const int q = c4 * 4 + j;                 // float4 idx 0..15
                float4 v = ok ? wp[q] : make_float4(0.f, 0.f, 0.f, 0.f);
                float vals[4] = {v.x, v.y, v.z, v.w};
#pragma unroll
                for (int e = 0; e < 4; e++) {
                    const int c = q * 4 + e;              // n-local 0..63
                    unsigned short h = bfu(vals[e]);
                    unsigned short l = bfu(vals[e] - bff(h));
                    Ahi[c * PADR + r64] = h;
                    Alo[c * PADR + r64] = l;
                }
            }
        }
        // ---- V tile: rows m (k), cols d. natural k-major store ----
        {
            const float4* vp = (const float4*)(V + (size_t)(ok ? mrow : 0) * DIM + d0);
#pragma unroll
            for (int j = 0; j < 4; j++) {
                const int q = c4 * 4 + j;
                float4 v = ok ? vp[q] : make_float4(0.f, 0.f, 0.f, 0.f);
                uint2 uh, ul;
                split4(v, uh, ul);
                const int so = (r64 * PADR + q * 4) * 2;
                *(uint2*)(smc + BA_BHI + so) = uh;
                *(uint2*)(smc + BA_BLO + so) = ul;
            }
        }
        __syncthreads();
#pragma unroll
        for (int ks = 0; ks < 4; ks++) {
            const int kk = ks * 16;
            unsigned int ahi[4], alo[4];
            {
                const unsigned int ad = sbase + a_off + (unsigned int)kk * 2;
                ldsm4(ahi[0], ahi[1], ahi[2], ahi[3], ad + BA_AHI);
                ldsm4(alo[0], alo[1], alo[2], alo[3], ad + BA_ALO);
            }
            unsigned int bhi[4][2], blo[4][2];
#pragma unroll
            for (int dh = 0; dh < 2; dh++) {
                const unsigned int bd = sbase +
                    (unsigned int)((kk + btr) * PADR + (wn * 32 + dh * 16 + btc)) * 2;
                unsigned int r0, r1, r2, r3;
                ldsm4t(r0, r1, r2, r3, bd + BA_BHI);
                bhi[2*dh][0] = r0; bhi[2*dh][1] = r1;
                bhi[2*dh+1][0] = r2; bhi[2*dh+1][1] = r3;
                ldsm4t(r0, r1, r2, r3, bd + BA_BLO);
                blo[2*dh][0] = r0; blo[2*dh][1] = r1;
                blo[2*dh+1][0] = r2; blo[2*dh+1][1] = r3;
            }
#pragma unroll
            for (int nt = 0; nt < 4; nt++) {
                mma16816(acc[nt], ahi[0], ahi[1], ahi[2], ahi[3], bhi[nt][0], bhi[nt][1]);
                mma16816(acc[nt], ahi[0], ahi[1], ahi[2], ahi[3], blo[nt][0], blo[nt][1]);
                mma16816(acc[nt], alo[0], alo[1], alo[2], alo[3], bhi[nt][0], bhi[nt][1]);
            }
        }
    }

    const int group = lane >> 2, tig = lane & 3;
#pragma unroll
    for (int nt = 0; nt < 4; nt++) {
        const int col = d0 + wn * 32 + nt * 8 + tig * 2;
#pragma unroll
        for (int h = 0; h < 2; h++) {
            const int row = n0 + wm * 16 + group + h * 8;
            *(float2*)(Y + (size_t)row * DIM + col) =
                make_float2(acc[nt][2 * h], acc[nt][2 * h + 1]);
        }
    }
}

// ---------------------------------------------------------------------------
__global__ void band_softmax(float* __restrict__ band)
{
    __shared__ float red[256];
    const int i = blockIdx.x;
    const int tid = threadIdx.x;
    const int i0 = i & ~63;
    const int jstart = i0 - 256;
    const int bs = (i < SEQ) ? 0 : SEQ;
    const int jmin = max(i - 255, bs);
    const int jmax = min(i + 255, bs + SEQ - 1);
    const int cmin = jmin - jstart, cmax = jmax - jstart;
    float* row = band + (size_t)i * BANDW;

    float m = -1e30f;
    for (int c = tid; c < BANDW; c += 256)
        if (c >= cmin && c <= cmax) m = fmaxf(m, row[c]);
    red[tid] = m; __syncthreads();
    for (int s = 128; s > 0; s >>= 1) {
        if (tid < s) red[tid] = fmaxf(red[tid], red[tid + s]);
        __syncthreads();
    }
    m = red[0]; __syncthreads();

    float ssum = 0.f;
    for (int c = tid; c < BANDW; c += 256)
        if (c >= cmin && c <= cmax) ssum += __expf(row[c] - m);
    red[tid] = ssum; __syncthreads();
    for (int s = 128; s > 0; s >>= 1) {
        if (tid < s) red[tid] += red[tid + s];
        __syncthreads();
    }
    const float inv = 1.f / red[0];

    for (int c = tid; c < BANDW; c += 256) {
        float v = (c >= cmin && c <= cmax) ? __expf(row[c] - m) * inv : 0.f;
        row[c] = v;
    }
}

// ---------------------------------------------------------------------------
__global__ void addln_acc(const float* __restrict__ A, const float* __restrict__ X,
                          const float* __restrict__ g, const float* __restrict__ bb,
                          float* __restrict__ ysum)
{
    __shared__ float red[256];
    const int row = blockIdx.x, tid = threadIdx.x;
    const size_t base = (size_t)row * DIM + tid * 4;
    float4 a = *(const float4*)(A + base);
    float4 x = *(const float4*)(X + base);
    float v0 = a.x + x.x, v1 = a.y + x.y, v2 = a.z + x.z, v3 = a.w + x.w;

    red[tid] = v0 + v1 + v2 + v3;
    __syncthreads();
    for (int s = 128; s > 0; s >>= 1) { if (tid < s) red[tid] += red[tid + s]; __syncthreads(); }
    const float mean = red[0] * (1.f / DIM);
    __syncthreads();

    const float d0 = v0 - mean, d1 = v1 - mean, d2 = v2 - mean, d3 = v3 - mean;
    red[tid] = d0 * d0 + d1 * d1 + d2 * d2 + d3 * d3;
    __syncthreads();
    for (int s = 128; s > 0; s >>= 1) { if (tid < s) red[tid] += red[tid + s]; __syncthreads(); }
    const float scale = 1.f / (sqrtf(red[0] * (1.f / (DIM - 1))) + LN_EPS);

    const int c = tid * 4;
    float4 gg = *(const float4*)(g + c);
    float4 bv = *(const float4*)(bb + c);
    float4 ys = *(float4*)(ysum + base);
    ys.x += gg.x * d0 * scale + bv.x;
    ys.y += gg.y * d1 * scale + bv.y;
    ys.z += gg.z * d2 * scale + bv.z;
    ys.w += gg.w * d3 * scale + bv.w;
    *(float4*)(ysum + base) = ys;
}

__global__ void ln_only(const float* __restrict__ H,
                        const float* __restrict__ g, const float* __restrict__ bb,
                        float* __restrict__ out)
{
    __shared__ float red[256];
    const int row = blockIdx.x, tid = threadIdx.x;
    const size_t base = (size_t)row * DIM + tid * 4;
    float4 h = *(const float4*)(H + base);
    red[tid] = h.x + h.y + h.z + h.w;
    __syncthreads();
    for (int s = 128; s > 0; s >>= 1) { if (tid < s) red[tid] += red[tid + s]; __syncthreads(); }
    const float mean = red[0] * (1.f / DIM);
    __syncthreads();

    const float d0 = h.x - mean, d1 = h.y - mean, d2 = h.z - mean, d3 = h.w - mean;
    red[tid] = d0 * d0 + d1 * d1 + d2 * d2 + d3 * d3;
    __syncthreads();
    for (int s = 128; s > 0; s >>= 1) { if (tid < s) red[tid] += red[tid + s]; __syncthreads(); }
    const float scale = 1.f / (sqrtf(red[0] * (1.f / (DIM - 1))) + LN_EPS);

    const int c = tid * 4;
    float4 gg = *(const float4*)(g + c);
    float4 bv = *(const float4*)(bb + c);
    float4 o;
    o.x = gg.x * d0 * scale + bv.x;
    o.y = gg.y * d1 * scale + bv.y;
    o.z = gg.z * d2 * scale + bv.z;
    o.w = gg.w * d3 * scale + bv.w;
    *(float4*)(out + base) = o;
}

__global__ void kd_dot(const float* __restrict__ H, const float* __restrict__ w,
                       const float* __restrict__ bias, float* __restrict__ out)
{
    __shared__ float red[256];
    const int row = blockIdx.x, tid = threadIdx.x;
    float4 h = *(const float4*)(H + (size_t)row * DIM + tid * 4);
    float4 ww = *(const float4*)(w + tid * 4);
    red[tid] = h.x * ww.x + h.y * ww.y + h.z * ww.z + h.w * ww.w;
    __syncthreads();
    for (int s = 128; s > 0; s >>= 1) { if (tid < s) red[tid] += red[tid + s]; __syncthreads(); }
    if (tid == 0) out[row] = red[0] + bias[0];
}

// ---------------------------------------------------------------------------
extern "C" void kernel_launch(void* const* d_in, const int* in_sizes, int n_in,
                              void* d_out, int out_size)
{
    (void)in_sizes; (void)n_in; (void)out_size;

    const float* x1   = (const float*)d_in[0];
    const float* x2   = (const float*)d_in[1];
    const float* x3   = (const float*)d_in[2];
    const float* Wk   = (const float*)d_in[3];
    const float* Wq   = (const float*)d_in[4];
    const float* Wv   = (const float*)d_in[5];
    const float* Wo   = (const float*)d_in[6];
    const float* ka_w = (const float*)d_in[7];
    const float* ka_b = (const float*)d_in[8];
    const float* kb_w = (const float*)d_in[9];
    const float* kb_b = (const float*)d_in[10];
    const float* kc_w = (const float*)d_in[11];
    const float* kc_b = (const float*)d_in[12];
    const float* kd_w = (const float*)d_in[13];
    const float* kd_b = (const float*)d_in[14];
    const float* g1   = (const float*)d_in[15];
    const float* b1   = (const float*)d_in[16];
    const float* g2   = (const float*)d_in[17];
    const float* b2   = (const float*)d_in[18];
    float* out = (float*)d_out;

    float* scratch = nullptr;
    cudaGetSymbolAddress((void**)&scratch, g_scratch);
    float* bK   = scratch + 0 * (size_t)RD;
    float* bQ   = scratch + 1 * (size_t)RD;
    float* bV   = scratch + 2 * (size_t)RD;
    float* bA   = scratch + 3 * (size_t)RD;
    float* ySum = scratch + 4 * (size_t)RD;
    float* band = scratch + 5 * (size_t)RD;

    cudaFuncSetAttribute(tgemm, cudaFuncAttributeMaxDynamicSharedMemorySize, SMT);
    cudaFuncSetAttribute(band_logits_mma, cudaFuncAttributeMaxDynamicSharedMemorySize, BL_SMT);
    cudaFuncSetAttribute(band_apply_mma, cudaFuncAttributeMaxDynamicSharedMemorySize, BA_SMT);

    const dim3 gT(DIM / 128, RTOT / 128);     // (8, 64)
    const dim3 gL(BANDW / 128, RTOT / 64);    // (5, 128)
    const dim3 gA(DIM / 64, RTOT / 64);       // (16, 128)

    cudaMemsetAsync(ySum, 0, sizeof(float) * (size_t)RD);

    const float* xs[3] = {x1, x2, x3};
    for (int t = 0; t < 3; t++) {
        const float* x = xs[t];
        tgemm<<<gT, 256, SMT>>>(x, Wk, nullptr, bK, DIM, 1.0f, 0);
        tgemm<<<gT, 256, SMT>>>(x, Wq, nullptr, bQ, DIM, 0.06f, 0);   // Q_SCALE
        tgemm<<<gT, 256, SMT>>>(x, Wv, nullptr, bV, DIM, 1.0f, 0);
        band_logits_mma<<<gL, 256, BL_SMT>>>(bQ, bK, band);
        band_softmax<<<RTOT, 256>>>(band);
        band_apply_mma<<<gA, 256, BA_SMT>>>(band, bV, bA);
        tgemm<<<gT, 256, SMT>>>(bA, Wo, nullptr, bK, DIM, 1.0f, 0);
        addln_acc<<<RTOT, 256>>>(bK, x, g1, b1, ySum);
    }

    tgemm<<<gT, 256, SMT>>>(ySum, ka_w, ka_b, bQ, DIM, 1.0f, 0);
    tgemm<<<gT, 256, SMT>>>(bQ, kb_w, kb_b, bV, DIM, 1.0f, 0);
    tgemm<<<gT, 256, SMT>>>(bV, kc_w, kc_b, bQ, DIM, 1.0f, 1);       // + ReLU
    ln_only<<<RTOT, 256>>>(bQ, g2, b2, bV);
    kd_dot<<<RTOT, 256>>>(bV, kd_w, kd_b, out);
}

// round 6
// speedup vs baseline: 2.5667x; 1.0901x over previous
#include <cuda_runtime.h>
#include <cuda_bf16.h>
#include <cstdint>
#include <math.h>

#define RTOT  8192              // B*N rows
#define SEQ   4096              // per-batch sequence length
#define DIM   1024
#define BANDW 640               // padded band width per row-block
#define LN_EPS 1e-6f
#define RD (RTOT * DIM)

// Scratch (float units):
//  [0, RD/2)      Khi (bf16)      [RD/2, RD)   Klo
//  [RD, 3RD/2)    Qhi             [3RD/2, 2RD) Qlo
//  [2RD, 5RD/2)   Vhi             [5RD/2, 3RD) Vlo
//  [3RD, 4RD)     bA (fp32)
//  [4RD, 5RD)     ySum (fp32)
//  [5RD, ...)     band (fp32, RTOT*BANDW)
__device__ float g_scratch[5 * RD + (size_t)RTOT * BANDW];

// ============================================================================
// mma.sync helpers
// ============================================================================
__device__ __forceinline__ unsigned int smem_to_u32(const void* p) {
    unsigned int a;
    asm("{ .reg .u64 t; cvta.to.shared.u64 t, %1; cvt.u32.u64 %0, t; }"
        : "=r"(a) : "l"(p));
    return a;
}

__device__ __forceinline__ void ldsm4(unsigned int& r0, unsigned int& r1,
                                      unsigned int& r2, unsigned int& r3,
                                      unsigned int addr) {
    asm volatile("ldmatrix.sync.aligned.m8n8.x4.shared.b16 {%0,%1,%2,%3}, [%4];"
                 : "=r"(r0), "=r"(r1), "=r"(r2), "=r"(r3) : "r"(addr));
}
__device__ __forceinline__ void ldsm4t(unsigned int& r0, unsigned int& r1,
                                       unsigned int& r2, unsigned int& r3,
                                       unsigned int addr) {
    asm volatile("ldmatrix.sync.aligned.m8n8.x4.trans.shared.b16 {%0,%1,%2,%3}, [%4];"
                 : "=r"(r0), "=r"(r1), "=r"(r2), "=r"(r3) : "r"(addr));
}

__device__ __forceinline__ void mma16816(float* c, unsigned int a0, unsigned int a1,
                                         unsigned int a2, unsigned int a3,
                                         unsigned int b0, unsigned int b1) {
    asm volatile(
        "mma.sync.aligned.m16n8k16.row.col.f32.bf16.bf16.f32 "
        "{%0,%1,%2,%3}, {%4,%5,%6,%7}, {%8,%9}, {%0,%1,%2,%3};"
        : "+f"(c[0]), "+f"(c[1]), "+f"(c[2]), "+f"(c[3])
        : "r"(a0), "r"(a1), "r"(a2), "r"(a3), "r"(b0), "r"(b1));
}

__device__ __forceinline__ unsigned short bfu(float f) {
    return __bfloat16_as_ushort(__float2bfloat16(f));
}
__device__ __forceinline__ float bff(unsigned short u) {
    return __bfloat162float(__ushort_as_bfloat16(u));
}

__device__ __forceinline__ void split4(float4 v, uint2& uh, uint2& ul) {
    unsigned short hx = bfu(v.x), hy = bfu(v.y), hz = bfu(v.z), hw = bfu(v.w);
    uh = make_uint2((unsigned int)hx | ((unsigned int)hy << 16),
                    (unsigned int)hz | ((unsigned int)hw << 16));
    unsigned short lx = bfu(v.x - bff(hx)), ly = bfu(v.y - bff(hy));
    unsigned short lz = bfu(v.z - bff(hz)), lw = bfu(v.w - bff(hw));
    ul = make_uint2((unsigned int)lx | ((unsigned int)ly << 16),
                    (unsigned int)lz | ((unsigned int)lw << 16));
}

// ============================================================================
// tgemm: acc = alpha*(A[M,1024] @ B[Nn,1024]^T). Output either:
//   Chi/Clo non-null  -> split bf16 planes (bias/relu ignored)
//   else              -> fp32 C (+bias)(+relu)
// CTA 128x128, BK=64, 8 warps (4M x 2N), bf16-split-3 accumulation.
// ============================================================================
#define PADR 72
#define TILE_B (128 * PADR * 2)
#define OFF_AHI 0
#define OFF_ALO (1 * TILE_B)
#define OFF_BHI (2 * TILE_B)
#define OFF_BLO (3 * TILE_B)
#define SMT     (4 * TILE_B)

__global__ void __launch_bounds__(256, 2)
tgemm(const float* __restrict__ A, const float* __restrict__ B,
      const float* __restrict__ bias, float* __restrict__ C,
      __nv_bfloat16* __restrict__ Chi, __nv_bfloat16* __restrict__ Clo,
      int Nn, float alpha, int relu)
{
    extern __shared__ __align__(16) char smc[];
    const unsigned int sbase = smem_to_u32(smc);
    const int tid = threadIdx.x;
    const int lane = tid & 31;
    const int wid = tid >> 5;
    const int wm = wid & 3;
    const int wn = wid >> 2;
    const int m0 = blockIdx.y << 7;
    const int n0 = blockIdx.x << 7;

    float acc[2][8][4];
#pragma unroll
    for (int i = 0; i < 2; i++)
#pragma unroll
        for (int j = 0; j < 8; j++)
#pragma unroll
            for (int c = 0; c < 4; c++) acc[i][j][c] = 0.f;

    const int lrow = tid >> 2;
    const int lseg = (tid & 3) << 2;

    const unsigned int a_off =
        (unsigned int)((wm * 32 + (lane & 15)) * PADR + ((lane >> 4) << 3)) * 2;
    const unsigned int b_off =
        (unsigned int)((wn * 64 + (lane & 7) + ((lane >> 4) << 3)) * PADR +
                       (((lane >> 3) & 1) << 3)) * 2;

    for (int kc = 0; kc < DIM / 64; kc++) {
        const int k0 = kc * 64;
        __syncthreads();
#pragma unroll
        for (int half = 0; half < 2; half++) {
            const int r = lrow + half * 64;
            const float4* ap = (const float4*)(A + (size_t)(m0 + r) * DIM + k0);
            const float4* bp = (const float4*)(B + (size_t)(n0 + r) * DIM + k0);
#pragma unroll
            for (int j = 0; j < 4; j++) {
                const int q = lseg + j;
                uint2 uh, ul;
                split4(ap[q], uh, ul);
                const int so = (r * PADR + q * 4) * 2;
                *(uint2*)(smc + OFF_AHI + so) = uh;
                *(uint2*)(smc + OFF_ALO + so) = ul;
                split4(bp[q], uh, ul);
                *(uint2*)(smc + OFF_BHI + so) = uh;
                *(uint2*)(smc + OFF_BLO + so) = ul;
            }
        }
        __syncthreads();
#pragma unroll
        for (int ks = 0; ks < 4; ks++) {
            const unsigned int kb = (unsigned int)(ks * 16) * 2;
            unsigned int ahi[2][4], alo[2][4];
#pragma unroll
            for (int mt = 0; mt < 2; mt++) {
                const unsigned int ad = sbase + (unsigned int)(mt * 16 * PADR * 2) + a_off + kb;
                ldsm4(ahi[mt][0], ahi[mt][1], ahi[mt][2], ahi[mt][3], ad + OFF_AHI);
                ldsm4(alo[mt][0], alo[mt][1], alo[mt][2], alo[mt][3], ad + OFF_ALO);
            }
            unsigned int bhi[8][2], blo[8][2];
#pragma unroll
            for (int np = 0; np < 4; np++) {
                const unsigned int bd = sbase + (unsigned int)(np * 16 * PADR * 2) + b_off + kb;
                unsigned int r0, r1, r2, r3;
                ldsm4(r0, r1, r2, r3, bd + OFF_BHI);
                bhi[2*np][0] = r0; bhi[2*np][1] = r1;
                bhi[2*np+1][0] = r2; bhi[2*np+1][1] = r3;
                ldsm4(r0, r1, r2, r3, bd + OFF_BLO);
                blo[2*np][0] = r0; blo[2*np][1] = r1;
                blo[2*np+1][0] = r2; blo[2*np+1][1] = r3;
            }
#pragma unroll
            for (int mt = 0; mt < 2; mt++)
#pragma unroll
                for (int nt = 0; nt < 8; nt++) {
                    mma16816(acc[mt][nt], ahi[mt][0], ahi[mt][1], ahi[mt][2], ahi[mt][3],
                             bhi[nt][0], bhi[nt][1]);
                    mma16816(acc[mt][nt], ahi[mt][0], ahi[mt][1], ahi[mt][2], ahi[mt][3],
                             blo[nt][0], blo[nt][1]);
                    mma16816(acc[mt][nt], alo[mt][0], alo[mt][1], alo[mt][2], alo[mt][3],
                             bhi[nt][0], bhi[nt][1]);
                }
        }
    }

    const int group = lane >> 2, tig = lane & 3;
    if (Chi) {
        // split-bf16 output planes
#pragma unroll
        for (int mt = 0; mt < 2; mt++)
#pragma unroll
            for (int nt = 0; nt < 8; nt++) {
                const int col = n0 + wn * 64 + nt * 8 + tig * 2;
#pragma unroll
                for (int h = 0; h < 2; h++) {
                    const int row = m0 + wm * 32 + mt * 16 + group + h * 8;
                    float v0 = alpha * acc[mt][nt][2 * h];
                    float v1 = alpha * acc[mt][nt][2 * h + 1];
                    unsigned short h0 = bfu(v0), h1 = bfu(v1);
                    unsigned short l0 = bfu(v0 - bff(h0)), l1 = bfu(v1 - bff(h1));
                    const size_t o = (size_t)row * Nn + col;
                    *(unsigned int*)(Chi + o) = (unsigned int)h0 | ((unsigned int)h1 << 16);
                    *(unsigned int*)(Clo + o) = (unsigned int)l0 | ((unsigned int)l1 << 16);
                }
            }
    } else {
#pragma unroll
        for (int mt = 0; mt < 2; mt++)
#pragma unroll
            for (int nt = 0; nt < 8; nt++) {
                const int col = n0 + wn * 64 + nt * 8 + tig * 2;
                float bx = 0.f, by = 0.f;
                if (bias) { bx = bias[col]; by = bias[col + 1]; }
#pragma unroll
                for (int h = 0; h < 2; h++) {
                    const int row = m0 + wm * 32 + mt * 16 + group + h * 8;
                    float v0 = alpha * acc[mt][nt][2 * h] + bx;
                    float v1 = alpha * acc[mt][nt][2 * h + 1] + by;
                    if (relu) { v0 = fmaxf(v0, 0.f); v1 = fmaxf(v1, 0.f); }
                    *(float2*)(C + (size_t)row * Nn + col) = make_float2(v0, v1);
                }
            }
    }
}

// ============================================================================
// band_logits_mma: band[i0+r][cb*128+c] = Q[i0+r] . K[i0-256+cb*128+c]
// Q/K pre-split bf16 planes. CTA 64(M) x 128(N), BK=64. No conversion.
// ============================================================================
#define BL_AHI 0
#define BL_ALO (64 * PADR * 2)
#define BL_BHI (2 * 64 * PADR * 2)
#define BL_BLO (BL_BHI + 128 * PADR * 2)
#define BL_SMT (BL_BLO + 128 * PADR * 2)     // 55296

__global__ void __launch_bounds__(256, 2)
band_logits_mma(const __nv_bfloat16* __restrict__ Qhi, const __nv_bfloat16* __restrict__ Qlo,
                const __nv_bfloat16* __restrict__ Khi, const __nv_bfloat16* __restrict__ Klo,
                float* __restrict__ band)
{
    extern __shared__ __align__(16) char smc[];
    const unsigned int sbase = smem_to_u32(smc);
    const int tid = threadIdx.x;
    const int lane = tid & 31;
    const int wid = tid >> 5;
    const int wm = wid & 1;
    const int wn = wid >> 1;
    const int i0 = blockIdx.y << 6;
    const int j0 = i0 - 256 + (blockIdx.x << 7);

    float acc[2][4][4];
#pragma unroll
    for (int i = 0; i < 2; i++)
#pragma unroll
        for (int j = 0; j < 4; j++)
#pragma unroll
            for (int c = 0; c < 4; c++) acc[i][j][c] = 0.f;

    const unsigned int a_off =
        (unsigned int)((wm * 32 + (lane & 15)) * PADR + ((lane >> 4) << 3)) * 2;
    const unsigned int b_off =
        (unsigned int)((wn * 32 + (lane & 7) + ((lane >> 4) << 3)) * PADR +
                       (((lane >> 3) & 1) << 3)) * 2;

    const int ar = tid >> 2;             // 0..63 A row (4 threads/row)
    const int aq = (tid & 3) << 1;       // uint4 idx base (2 per thread)
    const int br = tid >> 1;             // 0..127 B row (2 threads/row)
    const int bq = (tid & 1) << 2;       // uint4 idx base (4 per thread)
    const int jrow = j0 + br;
    const bool bok = (jrow >= 0) && (jrow < RTOT);
    const uint4 z4 = make_uint4(0, 0, 0, 0);

    for (int kc = 0; kc < DIM / 64; kc++) {
        const int k0 = kc * 64;
        __syncthreads();
        {
            const uint4* ah = (const uint4*)(Qhi + (size_t)(i0 + ar) * DIM + k0);
            const uint4* al = (const uint4*)(Qlo + (size_t)(i0 + ar) * DIM + k0);
#pragma unroll
            for (int j = 0; j < 2; j++) {
                const int q = aq + j;                    // 0..7
                const int so = (ar * PADR + q * 8) * 2;
                *(uint4*)(smc + BL_AHI + so) = ah[q];
                *(uint4*)(smc + BL_ALO + so) = al[q];
            }
        }
        {
            const uint4* bh = (const uint4*)(Khi + (size_t)(bok ? jrow : 0) * DIM + k0);
            const uint4* bl = (const uint4*)(Klo + (size_t)(bok ? jrow : 0) * DIM + k0);
#pragma unroll
            for (int j = 0; j < 4; j++) {
                const int q = bq + j;                    // 0..7
                const int so = (br * PADR + q * 8) * 2;
                *(uint4*)(smc + BL_BHI + so) = bok ? bh[q] : z4;
                *(uint4*)(smc + BL_BLO + so) = bok ? bl[q] : z4;
            }
        }
        __syncthreads();
#pragma unroll
        for (int ks = 0; ks < 4; ks++) {
            const unsigned int kb = (unsigned int)(ks * 16) * 2;
            unsigned int ahi[2][4], alo[2][4];
#pragma unroll
            for (int mt = 0; mt < 2; mt++) {
                const unsigned int ad = sbase + (unsigned int)(mt * 16 * PADR * 2) + a_off + kb;
                ldsm4(ahi[mt][0], ahi[mt][1], ahi[mt][2], ahi[mt][3], ad + BL_AHI);
                ldsm4(alo[mt][0], alo[mt][1], alo[mt][2], alo[mt][3], ad + BL_ALO);
            }
            unsigned int bhi[4][2], blo[4][2];
#pragma unroll
            for (int np = 0; np < 2; np++) {
                const unsigned int bd = sbase + (unsigned int)(np * 16 * PADR * 2) + b_off + kb;
                unsigned int r0, r1, r2, r3;
                ldsm4(r0, r1, r2, r3, bd + BL_BHI);
                bhi[2*np][0] = r0; bhi[2*np][1] = r1;
                bhi[2*np+1][0] = r2; bhi[2*np+1][1] = r3;
                ldsm4(r0, r1, r2, r3, bd + BL_BLO);
                blo[2*np][0] = r0; blo[2*np][1] = r1;
                blo[2*np+1][0] = r2; blo[2*np+1][1] = r3;
            }
#pragma unroll
            for (int mt = 0; mt < 2; mt++)
#pragma unroll
                for (int nt = 0; nt < 4; nt++) {
                    mma16816(acc[mt][nt], ahi[mt][0], ahi[mt][1], ahi[mt][2], ahi[mt][3],
                             bhi[nt][0], bhi[nt][1]);
                    mma16816(acc[mt][nt], ahi[mt][0], ahi[mt][1], ahi[mt][2], ahi[mt][3],
                             blo[nt][0], blo[nt][1]);
                    mma16816(acc[mt][nt], alo[mt][0], alo[mt][1], alo[mt][2], alo[mt][3],
                             bhi[nt][0], bhi[nt][1]);
                }
        }
    }

    const int group = lane >> 2, tig = lane & 3;
#pragma unroll
    for (int mt = 0; mt < 2; mt++)
#pragma unroll
        for (int nt = 0; nt < 4; nt++) {
            const int col = (blockIdx.x << 7) + wn * 32 + nt * 8 + tig * 2;
#pragma unroll
            for (int h = 0; h < 2; h++) {
                const int row = i0 + wm * 32 + mt * 16 + group + h * 8;
                *(float2*)(band + (size_t)row * BANDW + col) =
                    make_float2(acc[mt][nt][2 * h], acc[mt][nt][2 * h + 1]);
            }
        }
}

// ============================================================================
// band_apply_mma: Y[n,d] = sum_m w[m,n] * V[m,d]. V pre-split bf16 planes.
// CTA 64(n) x 64(d), 9 chunks of 64 m. A = w^T (split in-kernel, transposed
// store); B = V k-major via ldmatrix.trans.
// ============================================================================
#define BA_AHI 0
#define BA_ALO (64 * PADR * 2)
#define BA_BHI (2 * 64 * PADR * 2)
#define BA_BLO (3 * 64 * PADR * 2)
#define BA_SMT (4 * 64 * PADR * 2)          // 36864

__global__ void __launch_bounds__(256, 2)
band_apply_mma(const float* __restrict__ band,
               const __nv_bfloat16* __restrict__ Vhi, const __nv_bfloat16* __restrict__ Vlo,
               float* __restrict__ Y)
{
    extern __shared__ __align__(16) char smc[];
    const unsigned int sbase = smem_to_u32(smc);
    const int tid = threadIdx.x;
    const int lane = tid & 31;
    const int wid = tid >> 5;
    const int wm = wid & 3;
    const int wn = wid >> 2;
    const int n0 = blockIdx.y << 6;
    const int d0 = blockIdx.x << 6;

    float acc[4][4];
#pragma unroll
    for (int j = 0; j < 4; j++)
#pragma unroll
        for (int c = 0; c < 4; c++) acc[j][c] = 0.f;

    const unsigned int a_off =
        (unsigned int)((wm * 16 + (lane & 15)) * PADR + ((lane >> 4) << 3)) * 2;
    const int btr = (lane & 7) + (((lane >> 3) & 1) << 3);
    const int btc = (lane >> 4) << 3;

    const int r64 = tid >> 2;            // 0..63
    const int c4 = tid & 3;
    const uint4 z4 = make_uint4(0, 0, 0, 0);

    unsigned short* Ahi = (unsigned short*)(smc + BA_AHI);
    unsigned short* Alo = (unsigned short*)(smc + BA_ALO);

    for (int ch = 0; ch < 9; ch++) {
        const int mb = n0 - 256 + (ch << 6);
        const int coff = 512 - (ch << 6);
        const int mrow = mb + r64;
        const bool ok = (mrow >= 0) && (mrow < RTOT);
        __syncthreads();
        // w tile -> transposed split store (A = w^T)
        {
            const float4* wp = (const float4*)(band + (size_t)(ok ? mrow : 0) * BANDW + coff);
#pragma unroll
            for (int j = 0; j < 4; j++) {
                const int q = c4 * 4 + j;
                float4 v = ok ? wp[q] : make_float4(0.f, 0.f, 0.f, 0.f);
                float vals[4] = {v.x, v.y, v.z, v.w};
#pragma unroll
                for (int e = 0; e < 4; e++) {
                    const int c = q * 4 + e;
                    unsigned short h = bfu(vals[e]);
                    unsigned short l = bfu(vals[e] - bff(h));
                    Ahi[c * PADR + r64] = h;
                    Alo[c * PADR + r64] = l;
                }
            }
        }
        // V tile: direct bf16 copy, k-major
        {
            const uint4* vh = (const uint4*)(Vhi + (size_t)(ok ? mrow : 0) * DIM + d0);
            const uint4* vl = (const uint4*)(Vlo + (size_t)(ok ? mrow : 0) * DIM + d0);
#pragma unroll
            for (int j = 0; j < 2; j++) {
                const int q = c4 * 2 + j;                 // uint4 idx 0..7
                const int so = (r64 * PADR + q * 8) * 2;
                *(uint4*)(smc + BA_BHI + so) = ok ? vh[q] : z4;
                *(uint4*)(smc + BA_BLO + so) = ok ? vl[q] : z4;
            }
        }
        __syncthreads();
#pragma unroll
        for (int ks = 0; ks < 4; ks++) {
            const int kk = ks * 16;
            unsigned int ahi[4], alo[4];
            {
                const unsigned int ad = sbase + a_off + (unsigned int)kk * 2;
                ldsm4(ahi[0], ahi[1], ahi[2], ahi[3], ad + BA_AHI);
                ldsm4(alo[0], alo[1], alo[2], alo[3], ad + BA_ALO);
            }
            unsigned int bhi[4][2], blo[4][2];
#pragma unroll
            for (int dh = 0; dh < 2; dh++) {
                const unsigned int bd = sbase +
                    (unsigned int)((kk + btr) * PADR + (wn * 32 + dh * 16 + btc)) * 2;
                unsigned int r0, r1, r2, r3;
                ldsm4t(r0, r1, r2, r3, bd + BA_BHI);
                bhi[2*dh][0] = r0; bhi[2*dh][1] = r1;
                bhi[2*dh+1][0] = r2; bhi[2*dh+1][1] = r3;
                ldsm4t(r0, r1, r2, r3, bd + BA_BLO);
                blo[2*dh][0] = r0; blo[2*dh][1] = r1;
                blo[2*dh+1][0] = r2; blo[2*dh+1][1] = r3;
            }
#pragma unroll
            for (int nt = 0; nt < 4; nt++) {
                mma16816(acc[nt], ahi[0], ahi[1], ahi[2], ahi[3], bhi[nt][0], bhi[nt][1]);
                mma16816(acc[nt], ahi[0], ahi[1], ahi[2], ahi[3], blo[nt][0], blo[nt][1]);
                mma16816(acc[nt], alo[0], alo[1], alo[2], alo[3], bhi[nt][0], bhi[nt][1]);
            }
        }
    }

    const int group = lane >> 2, tig = lane & 3;
#pragma unroll
    for (int nt = 0; nt < 4; nt++) {
        const int col = d0 + wn * 32 + nt * 8 + tig * 2;
#pragma unroll
        for (int h = 0; h < 2; h++) {
            const int row = n0 + wm * 16 + group + h * 8;
            *(float2*)(Y + (size_t)row * DIM + col) =
                make_float2(acc[nt][2 * h], acc[nt][2 * h + 1]);
        }
    }
}

// ---------------------------------------------------------------------------
__global__ void band_softmax(float* __restrict__ band)
{
    __shared__ float red[256];
    const int i = blockIdx.x;
    const int tid = threadIdx.x;
    const int i0 = i & ~63;
    const int jstart = i0 - 256;
    const int bs = (i < SEQ) ? 0 : SEQ;
    const int jmin = max(i - 255, bs);
    const int jmax = min(i + 255, bs + SEQ - 1);
    const int cmin = jmin - jstart, cmax = jmax - jstart;
    float* row = band + (size_t)i * BANDW;

    float m = -1e30f;
    for (int c = tid; c < BANDW; c += 256)
        if (c >= cmin && c <= cmax) m = fmaxf(m, row[c]);
    red[tid] = m; __syncthreads();
    for (int s = 128; s > 0; s >>= 1) {
        if (tid < s) red[tid] = fmaxf(red[tid], red[tid + s]);
        __syncthreads();
    }
    m = red[0]; __syncthreads();

    float ssum = 0.f;
    for (int c = tid; c < BANDW; c += 256)
        if (c >= cmin && c <= cmax) ssum += __expf(row[c] - m);
    red[tid] = ssum; __syncthreads();
    for (int s = 128; s > 0; s >>= 1) {
        if (tid < s) red[tid] += red[tid + s];
        __syncthreads();
    }
    const float inv = 1.f / red[0];

    for (int c = tid; c < BANDW; c += 256) {
        float v = (c >= cmin && c <= cmax) ? __expf(row[c] - m) * inv : 0.f;
        row[c] = v;
    }
}

// ---------------------------------------------------------------------------
__global__ void addln_acc(const float* __restrict__ A, const float* __restrict__ X,
                          const float* __restrict__ g, const float* __restrict__ bb,
                          float* __restrict__ ysum)
{
    __shared__ float red[256];
    const int row = blockIdx.x, tid = threadIdx.x;
    const size_t base = (size_t)row * DIM + tid * 4;
    float4 a = *(const float4*)(A + base);
    float4 x = *(const float4*)(X + base);
    float v0 = a.x + x.x, v1 = a.y + x.y, v2 = a.z + x.z, v3 = a.w + x.w;

    red[tid] = v0 + v1 + v2 + v3;
    __syncthreads();
    for (int s = 128; s > 0; s >>= 1) { if (tid < s) red[tid] += red[tid + s]; __syncthreads(); }
    const float mean = red[0] * (1.f / DIM);
    __syncthreads();

    const float d0 = v0 - mean, d1 = v1 - mean, d2 = v2 - mean, d3 = v3 - mean;
    red[tid] = d0 * d0 + d1 * d1 + d2 * d2 + d3 * d3;
    __syncthreads();
    for (int s = 128; s > 0; s >>= 1) { if (tid < s) red[tid] += red[tid + s]; __syncthreads(); }
    const float scale = 1.f / (sqrtf(red[0] * (1.f / (DIM - 1))) + LN_EPS);

    const int c = tid * 4;
    float4 gg = *(const float4*)(g + c);
    float4 bv = *(const float4*)(bb + c);
    float4 ys = *(float4*)(ysum + base);
    ys.x += gg.x * d0 * scale + bv.x;
    ys.y += gg.y * d1 * scale + bv.y;
    ys.z += gg.z * d2 * scale + bv.z;
    ys.w += gg.w * d3 * scale + bv.w;
    *(float4*)(ysum + base) = ys;
}

__global__ void ln_only(const float* __restrict__ H,
                        const float* __restrict__ g, const float* __restrict__ bb,
                        float* __restrict__ out)
{
    __shared__ float red[256];
    const int row = blockIdx.x, tid = threadIdx.x;
    const size_t base = (size_t)row * DIM + tid * 4;
    float4 h = *(const float4*)(H + base);
    red[tid] = h.x + h.y + h.z + h.w;
    __syncthreads();
    for (int s = 128; s > 0; s >>= 1) { if (tid < s) red[tid] += red[tid + s]; __syncthreads(); }
    const float mean = red[0] * (1.f / DIM);
    __syncthreads();

    const float d0 = h.x - mean, d1 = h.y - mean, d2 = h.z - mean, d3 = h.w - mean;
    red[tid] = d0 * d0 + d1 * d1 + d2 * d2 + d3 * d3;
    __syncthreads();
    for (int s = 128; s > 0; s >>= 1) { if (tid < s) red[tid] += red[tid + s]; __syncthreads(); }
    const float scale = 1.f / (sqrtf(red[0] * (1.f / (DIM - 1))) + LN_EPS);

    const int c = tid * 4;
    float4 gg = *(const float4*)(g + c);
    float4 bv = *(const float4*)(bb + c);
    float4 o;
    o.x = gg.x * d0 * scale + bv.x;
    o.y = gg.y * d1 * scale + bv.y;
    o.z = gg.z * d2 * scale + bv.z;
    o.w = gg.w * d3 * scale + bv.w;
    *(float4*)(out + base) = o;
}

__global__ void kd_dot(const float* __restrict__ H, const float* __restrict__ w,
                       const float* __restrict__ bias, float* __restrict__ out)
{
    __shared__ float red[256];
    const int row = blockIdx.x, tid = threadIdx.x;
    float4 h = *(const float4*)(H + (size_t)row * DIM + tid * 4);
    float4 ww = *(const float4*)(w + tid * 4);
    red[tid] = h.x * ww.x + h.y * ww.y + h.z * ww.z + h.w * ww.w;
    __syncthreads();
    for (int s = 128; s > 0; s >>= 1) { if (tid < s) red[tid] += red[tid + s]; __syncthreads(); }
    if (tid == 0) out[row] = red[0] + bias[0];
}

// ---------------------------------------------------------------------------
extern "C" void kernel_launch(void* const* d_in, const int* in_sizes, int n_in,
                              void* d_out, int out_size)
{
    (void)in_sizes; (void)n_in; (void)out_size;

    const float* x1   = (const float*)d_in[0];
    const float* x2   = (const float*)d_in[1];
    const float* x3   = (const float*)d_in[2];
    const float* Wk   = (const float*)d_in[3];
    const float* Wq   = (const float*)d_in[4];
    const float* Wv   = (const float*)d_in[5];
    const float* Wo   = (const float*)d_in[6];
    const float* ka_w = (const float*)d_in[7];
    const float* ka_b = (const float*)d_in[8];
    const float* kb_w = (const float*)d_in[9];
    const float* kb_b = (const float*)d_in[10];
    const float* kc_w = (const float*)d_in[11];
    const float* kc_b = (const float*)d_in[12];
    const float* kd_w = (const float*)d_in[13];
    const float* kd_b = (const float*)d_in[14];
    const float* g1   = (const float*)d_in[15];
    const float* b1   = (const float*)d_in[16];
    const float* g2   = (const float*)d_in[17];
    const float* b2   = (const float*)d_in[18];
    float* out = (float*)d_out;

    float* scratch = nullptr;
    cudaGetSymbolAddress((void**)&scratch, g_scratch);
    __nv_bfloat16* Khi = (__nv_bfloat16*)(scratch);
    __nv_bfloat16* Klo = (__nv_bfloat16*)(scratch + (size_t)RD / 2);
    __nv_bfloat16* Qhi = (__nv_bfloat16*)(scratch + (size_t)RD);
    __nv_bfloat16* Qlo = (__nv_bfloat16*)(scratch + (size_t)RD * 3 / 2);
    __nv_bfloat16* Vhi = (__nv_bfloat16*)(scratch + (size_t)RD * 2);
    __nv_bfloat16* Vlo = (__nv_bfloat16*)(scratch + (size_t)RD * 5 / 2);
    float* bA   = scratch + (size_t)RD * 3;
    float* ySum = scratch + (size_t)RD * 4;
    float* band = scratch + (size_t)RD * 5;
    float* tmp1 = scratch + (size_t)RD * 0;   // reuse K/Q planes for MLP temps
    float* tmp2 = scratch + (size_t)RD * 1;

    cudaFuncSetAttribute(tgemm, cudaFuncAttributeMaxDynamicSharedMemorySize, SMT);
    cudaFuncSetAttribute(band_logits_mma, cudaFuncAttributeMaxDynamicSharedMemorySize, BL_SMT);
    cudaFuncSetAttribute(band_apply_mma, cudaFuncAttributeMaxDynamicSharedMemorySize, BA_SMT);

    const dim3 gT(DIM / 128, RTOT / 128);     // (8, 64)
    const dim3 gL(BANDW / 128, RTOT / 64);    // (5, 128)
    const dim3 gA(DIM / 64, RTOT / 64);       // (16, 128)

    cudaMemsetAsync(ySum, 0, sizeof(float) * (size_t)RD);

    const float* xs[3] = {x1, x2, x3};
    for (int t = 0; t < 3; t++) {
        const float* x = xs[t];
        tgemm<<<gT, 256, SMT>>>(x, Wk, nullptr, nullptr, Khi, Klo, DIM, 1.0f, 0);
        tgemm<<<gT, 256, SMT>>>(x, Wq, nullptr, nullptr, Qhi, Qlo, DIM, 0.06f, 0);
        tgemm<<<gT, 256, SMT>>>(x, Wv, nullptr, nullptr, Vhi, Vlo, DIM, 1.0f, 0);
        band_logits_mma<<<gL, 256, BL_SMT>>>(Qhi, Qlo, Khi, Klo, band);
        band_softmax<<<RTOT, 256>>>(band);
        band_apply_mma<<<gA, 256, BA_SMT>>>(band, Vhi, Vlo, bA);
        tgemm<<<gT, 256, SMT>>>(bA, Wo, nullptr, (t == 0) ? tmp1 : tmp2,
                                nullptr, nullptr, DIM, 1.0f, 0);
        // NOTE: attn-out buffer must not alias K/Q planes still in use.
        // K/Q/V planes are dead after band_apply of THIS tower, so reuse is safe.
        addln_acc<<<RTOT, 256>>>((t == 0) ? tmp1 : tmp2, x, g1, b1, ySum);
    }

    // MLP chain: K/Q/V planes dead; reuse fp32 views tmp1/tmp2/bA.
    tgemm<<<gT, 256, SMT>>>(ySum, ka_w, ka_b, tmp1, nullptr, nullptr, DIM, 1.0f, 0);
    tgemm<<<gT, 256, SMT>>>(tmp1, kb_w, kb_b, bA,  nullptr, nullptr, DIM, 1.0f, 0);
    tgemm<<<gT, 256, SMT>>>(bA, kc_w, kc_b, tmp1, nullptr, nullptr, DIM, 1.0f, 1);  // +ReLU
    ln_only<<<RTOT, 256>>>(tmp1, g2, b2, bA);
    kd_dot<<<RTOT, 256>>>(bA, kd_w, kd_b, out);
}